// round 6
// baseline (speedup 1.0000x reference)
#include <cuda_runtime.h>
#include <cstdint>

// Problem dims
#define SDIM 1024
#define NB   8
#define DDIM 1024
#define HH   16
#define DKH  64

// ---------------- scratch (device globals; no allocations allowed) ----------
__device__ float g_Qp[(size_t)NB * HH * SDIM * DKH];   // [N,H,S,DK]
__device__ float g_Qs[(size_t)NB * HH * SDIM * DKH];
__device__ float g_Kh[(size_t)NB * HH * SDIM * DKH];
__device__ float g_Vh[(size_t)NB * HH * SDIM * DKH];
__device__ float g_ctx0[(size_t)NB * SDIM * DDIM];     // [N,S,D]
__device__ float g_ctx1[(size_t)NB * SDIM * DDIM];
__device__ float g_madd[(size_t)NB * SDIM];            // 0 or -1e9 additive mask

// ---------------- mask canonicalization -------------------------------------
__global__ void mask_expand_kernel(const unsigned char* __restrict__ m,
                                   float* __restrict__ madd)
{
    __shared__ int s_big, s_nonmult4, s_anynz;
    const int t = threadIdx.x;               // 1024 threads, single block
    if (t == 0) { s_big = 0; s_nonmult4 = 0; s_anynz = 0; }
    __syncthreads();

    const int total = NB * SDIM;             // 8192 entries
    int big = 0, nonm4 = 0, anynz = 0;
    for (int i = t; i < total; i += 1024) {
        unsigned char b = m[i];
        if (b > 1) big = 1;
        if (b) { anynz = 1; if (i & 3) nonm4 = 1; }
    }
    if (big)   atomicOr(&s_big, 1);
    if (nonm4) atomicOr(&s_nonmult4, 1);
    if (anynz) atomicOr(&s_anynz, 1);
    __syncthreads();

    const bool width4 = s_big || !s_nonmult4 || !s_anynz;

    for (int i = t; i < total; i += 1024) {
        unsigned char v;
        if (width4) {
            v = (unsigned char)(m[4 * i] | m[4 * i + 1] | m[4 * i + 2] | m[4 * i + 3]);
        } else {
            v = m[i];
        }
        madd[i] = v ? -1e9f : 0.f;
    }
}

// ---------------- tf32 mma helpers ------------------------------------------
__device__ __forceinline__ float to_tf32(float x) {
    float r;
    asm("cvt.rna.tf32.f32 %0, %1;" : "=f"(r) : "f"(x));
    return r;
}

__device__ __forceinline__ void mma_tf32_16x8x8(float* c, const uint32_t* a,
                                                const uint32_t* b)
{
    asm volatile(
        "mma.sync.aligned.m16n8k8.row.col.f32.tf32.tf32.f32 "
        "{%0,%1,%2,%3}, {%4,%5,%6,%7}, {%8,%9}, {%0,%1,%2,%3};"
        : "+f"(c[0]), "+f"(c[1]), "+f"(c[2]), "+f"(c[3])
        : "r"(a[0]), "r"(a[1]), "r"(a[2]), "r"(a[3]), "r"(b[0]), "r"(b[1]));
}

// ---------------- batched, pipelined tensor-core GEMM -----------------------
// C[m,dout] = sum_k A[m,k] * W[dout,k] + b[dout]; M=8192, N=K=1024.
// Block tile 128x128x16, 8 warps, warp tile 64x32; double-buffered smem with
// register prefetch -> one __syncthreads per K-step. blockIdx.z picks batch.
struct Batch4 {
    const float* A[4];
    const float* W[4];
    const float* bias[4];
    float* out[4];
};

template <int MODE>
__global__ void __launch_bounds__(256)
gemm_tc(Batch4 batch)
{
    constexpr int BM = 128, BN = 128, BK = 16, KD = 1024;
    constexpr int STR = 20;
    __shared__ float As[2][BM * STR];
    __shared__ float Bs[2][BN * STR];

    const int z = blockIdx.z;
    const float* __restrict__ A    = batch.A[z];
    const float* __restrict__ W    = batch.W[z];
    const float* __restrict__ bias = batch.bias[z];
    float* __restrict__ out        = batch.out[z];

    const int tid  = threadIdx.x;
    const int wid  = tid >> 5;
    const int lane = tid & 31;
    const int wm = wid & 1;
    const int wn = wid >> 1;
    const int m0 = blockIdx.y * BM;
    const int n0 = blockIdx.x * BN;

    const int r  = lane >> 2;
    const int cq = lane & 3;

    // per-thread load coordinates (2 float4 per operand)
    const int lrow0 = tid >> 2;
    const int lrow1 = (tid + 256) >> 2;
    const int lc4   = (tid & 3) << 2;

    const float* Aptr = A + (size_t)m0 * KD;
    const float* Wptr = W + (size_t)n0 * KD;

    float acc[4][4][4];
    #pragma unroll
    for (int mt = 0; mt < 4; mt++)
        #pragma unroll
        for (int nt = 0; nt < 4; nt++)
            #pragma unroll
            for (int i = 0; i < 4; i++) acc[mt][nt][i] = 0.f;

    float4 pa0, pa1, pb0, pb1;

    // prologue: load k0 = 0
    pa0 = *(const float4*)(Aptr + (size_t)lrow0 * KD + lc4);
    pa1 = *(const float4*)(Aptr + (size_t)lrow1 * KD + lc4);
    pb0 = *(const float4*)(Wptr + (size_t)lrow0 * KD + lc4);
    pb1 = *(const float4*)(Wptr + (size_t)lrow1 * KD + lc4);
    {
        float4 t;
        t.x = to_tf32(pa0.x); t.y = to_tf32(pa0.y); t.z = to_tf32(pa0.z); t.w = to_tf32(pa0.w);
        *(float4*)(As[0] + lrow0 * STR + lc4) = t;
        t.x = to_tf32(pa1.x); t.y = to_tf32(pa1.y); t.z = to_tf32(pa1.z); t.w = to_tf32(pa1.w);
        *(float4*)(As[0] + lrow1 * STR + lc4) = t;
        t.x = to_tf32(pb0.x); t.y = to_tf32(pb0.y); t.z = to_tf32(pb0.z); t.w = to_tf32(pb0.w);
        *(float4*)(Bs[0] + lrow0 * STR + lc4) = t;
        t.x = to_tf32(pb1.x); t.y = to_tf32(pb1.y); t.z = to_tf32(pb1.z); t.w = to_tf32(pb1.w);
        *(float4*)(Bs[0] + lrow1 * STR + lc4) = t;
    }
    __syncthreads();

    for (int it = 0; it < KD / BK; it++) {
        const int cur = it & 1;
        const int nxt = cur ^ 1;
        const bool more = (it + 1) < KD / BK;

        // prefetch next K-slab into registers (overlaps with mma below)
        if (more) {
            const int kn = (it + 1) * BK;
            pa0 = *(const float4*)(Aptr + (size_t)lrow0 * KD + kn + lc4);
            pa1 = *(const float4*)(Aptr + (size_t)lrow1 * KD + kn + lc4);
            pb0 = *(const float4*)(Wptr + (size_t)lrow0 * KD + kn + lc4);
            pb1 = *(const float4*)(Wptr + (size_t)lrow1 * KD + kn + lc4);
        }

        // compute on current stage
        const float* Asc = As[cur];
        const float* Bsc = Bs[cur];
        #pragma unroll
        for (int ks = 0; ks < 2; ks++) {
            const int kb = ks * 8;
            uint32_t af[4][4];
            #pragma unroll
            for (int mt = 0; mt < 4; mt++) {
                const int mrow = wm * 64 + mt * 16 + r;
                const float* p = Asc + mrow * STR + kb + cq;
                af[mt][0] = __float_as_uint(p[0]);
                af[mt][1] = __float_as_uint(p[8 * STR]);
                af[mt][2] = __float_as_uint(p[4]);
                af[mt][3] = __float_as_uint(p[8 * STR + 4]);
            }
            uint32_t bf[4][2];
            #pragma unroll
            for (int nt = 0; nt < 4; nt++) {
                const int nrow = wn * 32 + nt * 8 + r;
                const float* p = Bsc + nrow * STR + kb + cq;
                bf[nt][0] = __float_as_uint(p[0]);
                bf[nt][1] = __float_as_uint(p[4]);
            }
            #pragma unroll
            for (int mt = 0; mt < 4; mt++)
                #pragma unroll
                for (int nt = 0; nt < 4; nt++)
                    mma_tf32_16x8x8(acc[mt][nt], af[mt], bf[nt]);
        }

        // store prefetched slab into the other stage
        if (more) {
            float4 t;
            t.x = to_tf32(pa0.x); t.y = to_tf32(pa0.y); t.z = to_tf32(pa0.z); t.w = to_tf32(pa0.w);
            *(float4*)(As[nxt] + lrow0 * STR + lc4) = t;
            t.x = to_tf32(pa1.x); t.y = to_tf32(pa1.y); t.z = to_tf32(pa1.z); t.w = to_tf32(pa1.w);
            *(float4*)(As[nxt] + lrow1 * STR + lc4) = t;
            t.x = to_tf32(pb0.x); t.y = to_tf32(pb0.y); t.z = to_tf32(pb0.z); t.w = to_tf32(pb0.w);
            *(float4*)(Bs[nxt] + lrow0 * STR + lc4) = t;
            t.x = to_tf32(pb1.x); t.y = to_tf32(pb1.y); t.z = to_tf32(pb1.z); t.w = to_tf32(pb1.w);
            *(float4*)(Bs[nxt] + lrow1 * STR + lc4) = t;
        }
        __syncthreads();
    }

    // ---- epilogue: bias + scatter ----
    const int cpair = (lane & 3) * 2;
    #pragma unroll
    for (int nt = 0; nt < 4; nt++) {
        const int dout = n0 + wn * 32 + nt * 8 + cpair;
        const float2 bb = *(const float2*)(bias + dout);
        #pragma unroll
        for (int mt = 0; mt < 4; mt++) {
            #pragma unroll
            for (int half = 0; half < 2; half++) {
                const int m = m0 + wm * 64 + mt * 16 + r + half * 8;
                float2 v;
                v.x = acc[mt][nt][half * 2 + 0] + bb.x;
                v.y = acc[mt][nt][half * 2 + 1] + bb.y;
                if (MODE == 0) {
                    const int s = m >> 3, n = m & 7;
                    const int h = dout >> 6, dk = dout & 63;
                    *(float2*)(out + ((size_t)((n * HH + h) * SDIM + s)) * DKH + dk) = v;
                } else {
                    const int n = m >> 10, s = m & 1023;
                    *(float2*)(out + ((size_t)(s * NB + n)) * DDIM + dout) = v;
                }
            }
        }
    }
}

// ---------------- tensor-core flash attention --------------------------------
#define AQT 64
#define AKT 64
#define KS_STR 68
#define VS_STR 72
#define PS_STR 68

__global__ void __launch_bounds__(128)
attn_tc(const float* __restrict__ Qp, const float* __restrict__ Qsv,
        const float* __restrict__ Kh, const float* __restrict__ Vh,
        const float* __restrict__ maddg,
        float* __restrict__ ctx0, float* __restrict__ ctx1)
{
    extern __shared__ float sm[];
    float* Ks   = sm;                         // [64][KS_STR]
    float* Vs   = Ks + AKT * KS_STR;          // [64][VS_STR]
    float* Ps   = Vs + AKT * VS_STR;          // [64][PS_STR]
    float* madd = Ps + AQT * PS_STR;          // [64]

    const int nh = blockIdx.y;
    const int n  = nh / HH;
    const int stream = blockIdx.z;
    const int q0 = blockIdx.x * AQT;
    const int tid = threadIdx.x;
    const int wid = tid >> 5;
    const int lane = tid & 31;
    const int r  = lane >> 2;
    const int cq = lane & 3;

    const float* Qb = (stream ? Qsv : Qp) + (size_t)nh * SDIM * DKH;
    const float* Kb = Kh + (size_t)nh * SDIM * DKH;
    const float* Vb = Vh + (size_t)nh * SDIM * DKH;

    uint32_t qf[8][4];
    {
        const float* q0p = Qb + (size_t)(q0 + wid * 16 + r) * DKH;
        const float* q8p = q0p + 8 * DKH;
        #pragma unroll
        for (int ks = 0; ks < 8; ks++) {
            qf[ks][0] = __float_as_uint(to_tf32(q0p[ks * 8 + cq]));
            qf[ks][1] = __float_as_uint(to_tf32(q8p[ks * 8 + cq]));
            qf[ks][2] = __float_as_uint(to_tf32(q0p[ks * 8 + cq + 4]));
            qf[ks][3] = __float_as_uint(to_tf32(q8p[ks * 8 + cq + 4]));
        }
    }

    float o[8][4];
    #pragma unroll
    for (int nt = 0; nt < 8; nt++)
        #pragma unroll
        for (int i = 0; i < 4; i++) o[nt][i] = 0.f;
    float m0v = -1e30f, m1v = -1e30f, l0 = 0.f, l1 = 0.f;

    for (int kt = 0; kt < SDIM / AKT; kt++) {
        const int k0 = kt * AKT;
        {
            const float4* ksrc = (const float4*)(Kb + (size_t)k0 * DKH);
            const float4* vsrc = (const float4*)(Vb + (size_t)k0 * DKH);
            #pragma unroll
            for (int i = 0; i < 8; i++) {
                const int idx = tid + 128 * i;
                const int row = idx >> 4;
                const int c4  = (idx & 15) << 2;
                float4 kv = ksrc[idx];
                float4 vv = vsrc[idx];
                float4 k4, v4;
                k4.x = to_tf32(kv.x); k4.y = to_tf32(kv.y);
                k4.z = to_tf32(kv.z); k4.w = to_tf32(kv.w);
                v4.x = to_tf32(vv.x); v4.y = to_tf32(vv.y);
                v4.z = to_tf32(vv.z); v4.w = to_tf32(vv.w);
                *(float4*)(Ks + row * KS_STR + c4) = k4;
                *(float4*)(Vs + row * VS_STR + c4) = v4;
            }
            if (tid < AKT) madd[tid] = maddg[n * SDIM + k0 + tid];
        }
        __syncthreads();

        float sc[8][4];
        #pragma unroll
        for (int nt = 0; nt < 8; nt++)
            #pragma unroll
            for (int i = 0; i < 4; i++) sc[nt][i] = 0.f;

        #pragma unroll
        for (int ks = 0; ks < 8; ks++) {
            const int kb = ks * 8;
            #pragma unroll
            for (int nt = 0; nt < 8; nt++) {
                uint32_t b[2];
                const float* p = Ks + (nt * 8 + r) * KS_STR + kb + cq;
                b[0] = __float_as_uint(p[0]);
                b[1] = __float_as_uint(p[4]);
                mma_tf32_16x8x8(sc[nt], qf[ks], b);
            }
        }

        float tmax0 = -1e30f, tmax1 = -1e30f;
        #pragma unroll
        for (int nt = 0; nt < 8; nt++) {
            const int j = nt * 8 + 2 * cq;
            const float ma = madd[j], mb = madd[j + 1];
            sc[nt][0] = sc[nt][0] * 0.125f + ma;
            sc[nt][1] = sc[nt][1] * 0.125f + mb;
            sc[nt][2] = sc[nt][2] * 0.125f + ma;
            sc[nt][3] = sc[nt][3] * 0.125f + mb;
            tmax0 = fmaxf(tmax0, fmaxf(sc[nt][0], sc[nt][1]));
            tmax1 = fmaxf(tmax1, fmaxf(sc[nt][2], sc[nt][3]));
        }
        tmax0 = fmaxf(tmax0, __shfl_xor_sync(0xffffffffu, tmax0, 1));
        tmax0 = fmaxf(tmax0, __shfl_xor_sync(0xffffffffu, tmax0, 2));
        tmax1 = fmaxf(tmax1, __shfl_xor_sync(0xffffffffu, tmax1, 1));
        tmax1 = fmaxf(tmax1, __shfl_xor_sync(0xffffffffu, tmax1, 2));

        const float mn0 = fmaxf(m0v, tmax0);
        const float mn1 = fmaxf(m1v, tmax1);
        const float cr0 = __expf(m0v - mn0);
        const float cr1 = __expf(m1v - mn1);
        m0v = mn0; m1v = mn1;

        float ls0 = 0.f, ls1 = 0.f;
        float* prow0 = Ps + (wid * 16 + r) * PS_STR + 2 * cq;
        float* prow8 = prow0 + 8 * PS_STR;
        #pragma unroll
        for (int nt = 0; nt < 8; nt++) {
            const float p0 = __expf(sc[nt][0] - mn0);
            const float p1 = __expf(sc[nt][1] - mn0);
            const float p2 = __expf(sc[nt][2] - mn1);
            const float p3 = __expf(sc[nt][3] - mn1);
            ls0 += p0 + p1;
            ls1 += p2 + p3;
            float2 w0, w1;
            w0.x = to_tf32(p0); w0.y = to_tf32(p1);
            w1.x = to_tf32(p2); w1.y = to_tf32(p3);
            *(float2*)(prow0 + nt * 8) = w0;
            *(float2*)(prow8 + nt * 8) = w1;
            o[nt][0] *= cr0; o[nt][1] *= cr0;
            o[nt][2] *= cr1; o[nt][3] *= cr1;
        }
        ls0 += __shfl_xor_sync(0xffffffffu, ls0, 1);
        ls0 += __shfl_xor_sync(0xffffffffu, ls0, 2);
        ls1 += __shfl_xor_sync(0xffffffffu, ls1, 1);
        ls1 += __shfl_xor_sync(0xffffffffu, ls1, 2);
        l0 = l0 * cr0 + ls0;
        l1 = l1 * cr1 + ls1;

        __syncwarp();

        #pragma unroll
        for (int ks = 0; ks < 8; ks++) {
            const int kb = ks * 8;
            uint32_t a[4];
            const float* pa = Ps + (wid * 16 + r) * PS_STR + kb;
            a[0] = __float_as_uint(pa[cq]);
            a[1] = __float_as_uint(pa[8 * PS_STR + cq]);
            a[2] = __float_as_uint(pa[cq + 4]);
            a[3] = __float_as_uint(pa[8 * PS_STR + cq + 4]);
            #pragma unroll
            for (int nt = 0; nt < 8; nt++) {
                uint32_t b[2];
                const float* pv = Vs + (kb + cq) * VS_STR + nt * 8 + r;
                b[0] = __float_as_uint(pv[0]);
                b[1] = __float_as_uint(pv[4 * VS_STR]);
                mma_tf32_16x8x8(o[nt], a, b);
            }
        }
        __syncthreads();
    }

    const float inv0 = 1.f / l0;
    const float inv1 = 1.f / l1;
    const int h = nh % HH;
    const int q = q0 + wid * 16 + r;
    float* outp = (stream ? ctx1 : ctx0)
                + ((size_t)(n * SDIM + q)) * DDIM + h * DKH;
    float* outp8 = outp + 8 * DDIM;
    #pragma unroll
    for (int nt = 0; nt < 8; nt++) {
        const int dk = nt * 8 + 2 * cq;
        float2 v0, v1;
        v0.x = o[nt][0] * inv0; v0.y = o[nt][1] * inv0;
        v1.x = o[nt][2] * inv1; v1.y = o[nt][3] * inv1;
        *(float2*)(outp  + dk) = v0;
        *(float2*)(outp8 + dk) = v1;
    }
}

// ---------------------------------------------------------------------------
extern "C" void kernel_launch(void* const* d_in, const int* in_sizes, int n_in,
                              void* d_out, int out_size)
{
    const float* Qpoi = (const float*)d_in[0];
    const float* Qsvi = (const float*)d_in[1];
    const float* Kin  = (const float*)d_in[2];
    const float* Vin  = (const float*)d_in[3];
    const unsigned char* mask = (const unsigned char*)d_in[4];
    const float* wq_poi_w = (const float*)d_in[5];
    const float* wq_poi_b = (const float*)d_in[6];
    const float* wq_svi_w = (const float*)d_in[7];
    const float* wq_svi_b = (const float*)d_in[8];
    const float* wk_w = (const float*)d_in[9];
    const float* wk_b = (const float*)d_in[10];
    const float* wv_w = (const float*)d_in[11];
    const float* wv_b = (const float*)d_in[12];
    const float* fc_w = (const float*)d_in[13];
    const float* fc_b = (const float*)d_in[14];
    float* out = (float*)d_out;

    float *Qp, *Qs, *Kh, *Vh, *c0, *c1, *madd;
    cudaGetSymbolAddress((void**)&Qp, g_Qp);
    cudaGetSymbolAddress((void**)&Qs, g_Qs);
    cudaGetSymbolAddress((void**)&Kh, g_Kh);
    cudaGetSymbolAddress((void**)&Vh, g_Vh);
    cudaGetSymbolAddress((void**)&c0, g_ctx0);
    cudaGetSymbolAddress((void**)&c1, g_ctx1);
    cudaGetSymbolAddress((void**)&madd, g_madd);

    // 0) canonicalize padding mask
    mask_expand_kernel<<<1, 1024>>>(mask, madd);

    // 1) projections -> [N,H,S,DK] (one batched launch, z = 4)
    Batch4 proj;
    proj.A[0] = Qpoi;     proj.W[0] = wq_poi_w; proj.bias[0] = wq_poi_b; proj.out[0] = Qp;
    proj.A[1] = Qsvi;     proj.W[1] = wq_svi_w; proj.bias[1] = wq_svi_b; proj.out[1] = Qs;
    proj.A[2] = Kin;      proj.W[2] = wk_w;     proj.bias[2] = wk_b;     proj.out[2] = Kh;
    proj.A[3] = Vin;      proj.W[3] = wv_w;     proj.bias[3] = wv_b;     proj.out[3] = Vh;
    gemm_tc<0><<<dim3(DDIM / 128, (SDIM * NB) / 128, 4), 256>>>(proj);

    // 2) attention (tensor cores, tf32; both streams in z)
    const int smem = (AKT * KS_STR + AKT * VS_STR + AQT * PS_STR + AKT) * (int)sizeof(float);
    cudaFuncSetAttribute((const void*)attn_tc,
                         cudaFuncAttributeMaxDynamicSharedMemorySize, smem);
    attn_tc<<<dim3(SDIM / AQT, NB * HH, 2), 128, smem>>>(Qp, Qs, Kh, Vh, madd, c0, c1);

    // 3) output FC -> [S,N,D] (one batched launch, z = 2)
    Batch4 fc;
    fc.A[0] = c0; fc.W[0] = fc_w; fc.bias[0] = fc_b; fc.out[0] = out;
    fc.A[1] = c1; fc.W[1] = fc_w; fc.bias[1] = fc_b; fc.out[1] = out + (size_t)SDIM * NB * DDIM;
    fc.A[2] = c0; fc.W[2] = fc_w; fc.bias[2] = fc_b; fc.out[2] = out;  // unused
    fc.A[3] = c1; fc.W[3] = fc_w; fc.bias[3] = fc_b; fc.out[3] = out + (size_t)SDIM * NB * DDIM;  // unused
    gemm_tc<1><<<dim3(DDIM / 128, (SDIM * NB) / 128, 2), 256>>>(fc);
}

// round 7
// speedup vs baseline: 1.5557x; 1.5557x over previous
#include <cuda_runtime.h>
#include <cstdint>

// Problem dims
#define SDIM 1024
#define NB   8
#define DDIM 1024
#define HH   16
#define DKH  64

// ---------------- scratch (device globals; no allocations allowed) ----------
__device__ float g_Qp[(size_t)NB * HH * SDIM * DKH];   // [N,H,S,DK]
__device__ float g_Qs[(size_t)NB * HH * SDIM * DKH];
__device__ float g_Kh[(size_t)NB * HH * SDIM * DKH];
__device__ float g_Vh[(size_t)NB * HH * SDIM * DKH];
__device__ float g_ctx0[(size_t)NB * SDIM * DDIM];     // [N,S,D]
__device__ float g_ctx1[(size_t)NB * SDIM * DDIM];
__device__ float g_madd[(size_t)NB * SDIM];            // 0 or -1e9 additive mask

// ---------------- mask canonicalization -------------------------------------
__global__ void mask_expand_kernel(const unsigned char* __restrict__ m,
                                   float* __restrict__ madd)
{
    __shared__ int s_big, s_nonmult4, s_anynz;
    const int t = threadIdx.x;               // 1024 threads, single block
    if (t == 0) { s_big = 0; s_nonmult4 = 0; s_anynz = 0; }
    __syncthreads();

    const int total = NB * SDIM;             // 8192 entries
    int big = 0, nonm4 = 0, anynz = 0;
    for (int i = t; i < total; i += 1024) {
        unsigned char b = m[i];
        if (b > 1) big = 1;
        if (b) { anynz = 1; if (i & 3) nonm4 = 1; }
    }
    if (big)   atomicOr(&s_big, 1);
    if (nonm4) atomicOr(&s_nonmult4, 1);
    if (anynz) atomicOr(&s_anynz, 1);
    __syncthreads();

    const bool width4 = s_big || !s_nonmult4 || !s_anynz;

    for (int i = t; i < total; i += 1024) {
        unsigned char v;
        if (width4) {
            v = (unsigned char)(m[4 * i] | m[4 * i + 1] | m[4 * i + 2] | m[4 * i + 3]);
        } else {
            v = m[i];
        }
        madd[i] = v ? -1e9f : 0.f;
    }
}

// ---------------- tf32 mma helpers ------------------------------------------
__device__ __forceinline__ float to_tf32(float x) {
    float r;
    asm("cvt.rna.tf32.f32 %0, %1;" : "=f"(r) : "f"(x));
    return r;
}

__device__ __forceinline__ void mma_tf32_16x8x8(float* c, const uint32_t* a,
                                                const uint32_t* b)
{
    asm volatile(
        "mma.sync.aligned.m16n8k8.row.col.f32.tf32.tf32.f32 "
        "{%0,%1,%2,%3}, {%4,%5,%6,%7}, {%8,%9}, {%0,%1,%2,%3};"
        : "+f"(c[0]), "+f"(c[1]), "+f"(c[2]), "+f"(c[3])
        : "r"(a[0]), "r"(a[1]), "r"(a[2]), "r"(a[3]), "r"(b[0]), "r"(b[1]));
}

// k-permuted smem slab layout (16 k per row, 16 floats per row):
//   logical pos  p = (k%4)*4 + k/4   -> a thread's 4 frag values (k = cq,
//   cq+4, cq+8, cq+12) are the contiguous float4 at p = cq*4.
//   physical pos = p ^ swz(row), swz = ((row>>1)&3)<<2  (store de-conflict;
//   preserves float4 groups, read-side conflict-freedom unchanged).
__device__ __forceinline__ void store_slab(float* stage, int row, int c4i, float4 v)
{
    const int swz = ((row >> 1) & 3) << 2;
    float* p = stage + row * 16;
    p[(c4i      ) ^ swz] = to_tf32(v.x);   // k%4 = 0
    p[(c4i +  4) ^ swz] = to_tf32(v.y);   // k%4 = 1
    p[(c4i +  8) ^ swz] = to_tf32(v.z);   // k%4 = 2
    p[(c4i + 12) ^ swz] = to_tf32(v.w);   // k%4 = 3
}

// ---------------- batched, pipelined tensor-core GEMM -----------------------
// C[m,dout] = sum_k A[m,k] * W[dout,k] + b[dout]; M=8192, N=K=1024.
// Block tile 128x128x16, 8 warps (warp tile 64x32), double-buffered permuted
// smem, register prefetch, one __syncthreads per K-step. blockIdx.z = batch.
struct Batch4 {
    const float* A[4];
    const float* W[4];
    const float* bias[4];
    float* out[4];
};

template <int MODE>
__global__ void __launch_bounds__(256, 2)
gemm_tc(Batch4 batch)
{
    constexpr int BM = 128, BN = 128, BK = 16, KD = 1024;
    __shared__ float As[2][BM * 16];
    __shared__ float Bs[2][BN * 16];

    const int z = blockIdx.z;
    const float* __restrict__ A    = batch.A[z];
    const float* __restrict__ W    = batch.W[z];
    const float* __restrict__ bias = batch.bias[z];
    float* __restrict__ out        = batch.out[z];

    const int tid  = threadIdx.x;
    const int wid  = tid >> 5;
    const int lane = tid & 31;
    const int wm = wid & 1;
    const int wn = wid >> 1;
    const int m0 = blockIdx.y * BM;
    const int n0 = blockIdx.x * BN;

    const int r  = lane >> 2;
    const int cq = lane & 3;
    const int cqo = cq * 4;                   // contiguous frag offset (pre-swizzle)

    // per-thread fill coordinates (2 float4 per operand)
    const int lrow0 = tid >> 2;               // 0..63
    const int lrow1 = lrow0 + 64;             // 64..127
    const int c4i   = tid & 3;                // slab quarter
    const int lc4   = c4i << 2;               // k offset of the float4

    const float* Aptr = A + (size_t)m0 * KD;
    const float* Wptr = W + (size_t)n0 * KD;

    float acc[4][4][4];
    #pragma unroll
    for (int mt = 0; mt < 4; mt++)
        #pragma unroll
        for (int nt = 0; nt < 4; nt++)
            #pragma unroll
            for (int i = 0; i < 4; i++) acc[mt][nt][i] = 0.f;

    float4 pa0, pa1, pb0, pb1;

    // prologue: fill stage 0 with k0 = 0
    pa0 = *(const float4*)(Aptr + (size_t)lrow0 * KD + lc4);
    pa1 = *(const float4*)(Aptr + (size_t)lrow1 * KD + lc4);
    pb0 = *(const float4*)(Wptr + (size_t)lrow0 * KD + lc4);
    pb1 = *(const float4*)(Wptr + (size_t)lrow1 * KD + lc4);
    store_slab(As[0], lrow0, c4i, pa0);
    store_slab(As[0], lrow1, c4i, pa1);
    store_slab(Bs[0], lrow0, c4i, pb0);
    store_slab(Bs[0], lrow1, c4i, pb1);
    __syncthreads();

    for (int it = 0; it < KD / BK; it++) {
        const int cur = it & 1;
        const int nxt = cur ^ 1;
        const bool more = (it + 1) < KD / BK;

        if (more) {
            const int kn = (it + 1) * BK;
            pa0 = *(const float4*)(Aptr + (size_t)lrow0 * KD + kn + lc4);
            pa1 = *(const float4*)(Aptr + (size_t)lrow1 * KD + kn + lc4);
            pb0 = *(const float4*)(Wptr + (size_t)lrow0 * KD + kn + lc4);
            pb1 = *(const float4*)(Wptr + (size_t)lrow1 * KD + kn + lc4);
        }

        const float* Asc = As[cur];
        const float* Bsc = Bs[cur];

        // B fragments for both k8 steps: one LDS.128 per nt
        uint32_t bf0[4][2], bf1[4][2];
        #pragma unroll
        for (int nt = 0; nt < 4; nt++) {
            const int nrow = wn * 32 + nt * 8 + r;
            const int swz = ((nrow >> 1) & 3) << 2;
            const float4 bl = *(const float4*)(Bsc + nrow * 16 + (cqo ^ swz));
            bf0[nt][0] = __float_as_uint(bl.x);  // k = cq
            bf0[nt][1] = __float_as_uint(bl.y);  // k = cq+4
            bf1[nt][0] = __float_as_uint(bl.z);  // k = 8+cq
            bf1[nt][1] = __float_as_uint(bl.w);  // k = 12+cq
        }

        // A fragments: two LDS.128 per mt (rows r and r+8 share swz)
        #pragma unroll
        for (int mt = 0; mt < 4; mt++) {
            const int mr = wm * 64 + mt * 16 + r;
            const int swz = ((mr >> 1) & 3) << 2;
            const float4 lf0 = *(const float4*)(Asc + mr * 16 + (cqo ^ swz));
            const float4 lf8 = *(const float4*)(Asc + (mr + 8) * 16 + (cqo ^ swz));

            uint32_t a0[4], a1[4];
            a0[0] = __float_as_uint(lf0.x); a0[1] = __float_as_uint(lf8.x);
            a0[2] = __float_as_uint(lf0.y); a0[3] = __float_as_uint(lf8.y);
            a1[0] = __float_as_uint(lf0.z); a1[1] = __float_as_uint(lf8.z);
            a1[2] = __float_as_uint(lf0.w); a1[3] = __float_as_uint(lf8.w);

            #pragma unroll
            for (int nt = 0; nt < 4; nt++)
                mma_tf32_16x8x8(acc[mt][nt], a0, bf0[nt]);
            #pragma unroll
            for (int nt = 0; nt < 4; nt++)
                mma_tf32_16x8x8(acc[mt][nt], a1, bf1[nt]);
        }

        if (more) {
            store_slab(As[nxt], lrow0, c4i, pa0);
            store_slab(As[nxt], lrow1, c4i, pa1);
            store_slab(Bs[nxt], lrow0, c4i, pb0);
            store_slab(Bs[nxt], lrow1, c4i, pb1);
        }
        __syncthreads();
    }

    // ---- epilogue: bias + scatter ----
    const int cpair = (lane & 3) * 2;
    #pragma unroll
    for (int nt = 0; nt < 4; nt++) {
        const int dout = n0 + wn * 32 + nt * 8 + cpair;
        const float2 bb = *(const float2*)(bias + dout);
        #pragma unroll
        for (int mt = 0; mt < 4; mt++) {
            #pragma unroll
            for (int half = 0; half < 2; half++) {
                const int m = m0 + wm * 64 + mt * 16 + r + half * 8;
                float2 v;
                v.x = acc[mt][nt][half * 2 + 0] + bb.x;
                v.y = acc[mt][nt][half * 2 + 1] + bb.y;
                if (MODE == 0) {
                    const int s = m >> 3, n = m & 7;
                    const int h = dout >> 6, dk = dout & 63;
                    *(float2*)(out + ((size_t)((n * HH + h) * SDIM + s)) * DKH + dk) = v;
                } else {
                    const int n = m >> 10, s = m & 1023;
                    *(float2*)(out + ((size_t)(s * NB + n)) * DDIM + dout) = v;
                }
            }
        }
    }
}

// ---------------- tensor-core flash attention --------------------------------
#define AQT 64
#define AKT 64
#define KS_STR 68
#define VS_STR 72
#define PS_STR 68

__global__ void __launch_bounds__(128)
attn_tc(const float* __restrict__ Qp, const float* __restrict__ Qsv,
        const float* __restrict__ Kh, const float* __restrict__ Vh,
        const float* __restrict__ maddg,
        float* __restrict__ ctx0, float* __restrict__ ctx1)
{
    extern __shared__ float sm[];
    float* Ks   = sm;                         // [64][KS_STR]
    float* Vs   = Ks + AKT * KS_STR;          // [64][VS_STR]
    float* Ps   = Vs + AKT * VS_STR;          // [64][PS_STR]
    float* madd = Ps + AQT * PS_STR;          // [64]

    const int nh = blockIdx.y;
    const int n  = nh / HH;
    const int stream = blockIdx.z;
    const int q0 = blockIdx.x * AQT;
    const int tid = threadIdx.x;
    const int wid = tid >> 5;
    const int lane = tid & 31;
    const int r  = lane >> 2;
    const int cq = lane & 3;

    const float* Qb = (stream ? Qsv : Qp) + (size_t)nh * SDIM * DKH;
    const float* Kb = Kh + (size_t)nh * SDIM * DKH;
    const float* Vb = Vh + (size_t)nh * SDIM * DKH;

    uint32_t qf[8][4];
    {
        const float* q0p = Qb + (size_t)(q0 + wid * 16 + r) * DKH;
        const float* q8p = q0p + 8 * DKH;
        #pragma unroll
        for (int ks = 0; ks < 8; ks++) {
            qf[ks][0] = __float_as_uint(to_tf32(q0p[ks * 8 + cq]));
            qf[ks][1] = __float_as_uint(to_tf32(q8p[ks * 8 + cq]));
            qf[ks][2] = __float_as_uint(to_tf32(q0p[ks * 8 + cq + 4]));
            qf[ks][3] = __float_as_uint(to_tf32(q8p[ks * 8 + cq + 4]));
        }
    }

    float o[8][4];
    #pragma unroll
    for (int nt = 0; nt < 8; nt++)
        #pragma unroll
        for (int i = 0; i < 4; i++) o[nt][i] = 0.f;
    float m0v = -1e30f, m1v = -1e30f, l0 = 0.f, l1 = 0.f;

    for (int kt = 0; kt < SDIM / AKT; kt++) {
        const int k0 = kt * AKT;
        {
            const float4* ksrc = (const float4*)(Kb + (size_t)k0 * DKH);
            const float4* vsrc = (const float4*)(Vb + (size_t)k0 * DKH);
            #pragma unroll
            for (int i = 0; i < 8; i++) {
                const int idx = tid + 128 * i;
                const int row = idx >> 4;
                const int c4  = (idx & 15) << 2;
                float4 kv = ksrc[idx];
                float4 vv = vsrc[idx];
                float4 k4, v4;
                k4.x = to_tf32(kv.x); k4.y = to_tf32(kv.y);
                k4.z = to_tf32(kv.z); k4.w = to_tf32(kv.w);
                v4.x = to_tf32(vv.x); v4.y = to_tf32(vv.y);
                v4.z = to_tf32(vv.z); v4.w = to_tf32(vv.w);
                *(float4*)(Ks + row * KS_STR + c4) = k4;
                *(float4*)(Vs + row * VS_STR + c4) = v4;
            }
            if (tid < AKT) madd[tid] = maddg[n * SDIM + k0 + tid];
        }
        __syncthreads();

        float sc[8][4];
        #pragma unroll
        for (int nt = 0; nt < 8; nt++)
            #pragma unroll
            for (int i = 0; i < 4; i++) sc[nt][i] = 0.f;

        #pragma unroll
        for (int ks = 0; ks < 8; ks++) {
            const int kb = ks * 8;
            #pragma unroll
            for (int nt = 0; nt < 8; nt++) {
                uint32_t b[2];
                const float* p = Ks + (nt * 8 + r) * KS_STR + kb + cq;
                b[0] = __float_as_uint(p[0]);
                b[1] = __float_as_uint(p[4]);
                mma_tf32_16x8x8(sc[nt], qf[ks], b);
            }
        }

        float tmax0 = -1e30f, tmax1 = -1e30f;
        #pragma unroll
        for (int nt = 0; nt < 8; nt++) {
            const int j = nt * 8 + 2 * cq;
            const float ma = madd[j], mb = madd[j + 1];
            sc[nt][0] = sc[nt][0] * 0.125f + ma;
            sc[nt][1] = sc[nt][1] * 0.125f + mb;
            sc[nt][2] = sc[nt][2] * 0.125f + ma;
            sc[nt][3] = sc[nt][3] * 0.125f + mb;
            tmax0 = fmaxf(tmax0, fmaxf(sc[nt][0], sc[nt][1]));
            tmax1 = fmaxf(tmax1, fmaxf(sc[nt][2], sc[nt][3]));
        }
        tmax0 = fmaxf(tmax0, __shfl_xor_sync(0xffffffffu, tmax0, 1));
        tmax0 = fmaxf(tmax0, __shfl_xor_sync(0xffffffffu, tmax0, 2));
        tmax1 = fmaxf(tmax1, __shfl_xor_sync(0xffffffffu, tmax1, 1));
        tmax1 = fmaxf(tmax1, __shfl_xor_sync(0xffffffffu, tmax1, 2));

        const float mn0 = fmaxf(m0v, tmax0);
        const float mn1 = fmaxf(m1v, tmax1);
        const float cr0 = __expf(m0v - mn0);
        const float cr1 = __expf(m1v - mn1);
        m0v = mn0; m1v = mn1;

        float ls0 = 0.f, ls1 = 0.f;
        float* prow0 = Ps + (wid * 16 + r) * PS_STR + 2 * cq;
        float* prow8 = prow0 + 8 * PS_STR;
        #pragma unroll
        for (int nt = 0; nt < 8; nt++) {
            const float p0 = __expf(sc[nt][0] - mn0);
            const float p1 = __expf(sc[nt][1] - mn0);
            const float p2 = __expf(sc[nt][2] - mn1);
            const float p3 = __expf(sc[nt][3] - mn1);
            ls0 += p0 + p1;
            ls1 += p2 + p3;
            float2 w0, w1;
            w0.x = to_tf32(p0); w0.y = to_tf32(p1);
            w1.x = to_tf32(p2); w1.y = to_tf32(p3);
            *(float2*)(prow0 + nt * 8) = w0;
            *(float2*)(prow8 + nt * 8) = w1;
            o[nt][0] *= cr0; o[nt][1] *= cr0;
            o[nt][2] *= cr1; o[nt][3] *= cr1;
        }
        ls0 += __shfl_xor_sync(0xffffffffu, ls0, 1);
        ls0 += __shfl_xor_sync(0xffffffffu, ls0, 2);
        ls1 += __shfl_xor_sync(0xffffffffu, ls1, 1);
        ls1 += __shfl_xor_sync(0xffffffffu, ls1, 2);
        l0 = l0 * cr0 + ls0;
        l1 = l1 * cr1 + ls1;

        __syncwarp();

        #pragma unroll
        for (int ks = 0; ks < 8; ks++) {
            const int kb = ks * 8;
            uint32_t a[4];
            const float* pa = Ps + (wid * 16 + r) * PS_STR + kb;
            a[0] = __float_as_uint(pa[cq]);
            a[1] = __float_as_uint(pa[8 * PS_STR + cq]);
            a[2] = __float_as_uint(pa[cq + 4]);
            a[3] = __float_as_uint(pa[8 * PS_STR + cq + 4]);
            #pragma unroll
            for (int nt = 0; nt < 8; nt++) {
                uint32_t b[2];
                const float* pv = Vs + (kb + cq) * VS_STR + nt * 8 + r;
                b[0] = __float_as_uint(pv[0]);
                b[1] = __float_as_uint(pv[4 * VS_STR]);
                mma_tf32_16x8x8(o[nt], a, b);
            }
        }
        __syncthreads();
    }

    const float inv0 = 1.f / l0;
    const float inv1 = 1.f / l1;
    const int h = nh % HH;
    const int q = q0 + wid * 16 + r;
    float* outp = (stream ? ctx1 : ctx0)
                + ((size_t)(n * SDIM + q)) * DDIM + h * DKH;
    float* outp8 = outp + 8 * DDIM;
    #pragma unroll
    for (int nt = 0; nt < 8; nt++) {
        const int dk = nt * 8 + 2 * cq;
        float2 v0, v1;
        v0.x = o[nt][0] * inv0; v0.y = o[nt][1] * inv0;
        v1.x = o[nt][2] * inv1; v1.y = o[nt][3] * inv1;
        *(float2*)(outp  + dk) = v0;
        *(float2*)(outp8 + dk) = v1;
    }
}

// ---------------------------------------------------------------------------
extern "C" void kernel_launch(void* const* d_in, const int* in_sizes, int n_in,
                              void* d_out, int out_size)
{
    const float* Qpoi = (const float*)d_in[0];
    const float* Qsvi = (const float*)d_in[1];
    const float* Kin  = (const float*)d_in[2];
    const float* Vin  = (const float*)d_in[3];
    const unsigned char* mask = (const unsigned char*)d_in[4];
    const float* wq_poi_w = (const float*)d_in[5];
    const float* wq_poi_b = (const float*)d_in[6];
    const float* wq_svi_w = (const float*)d_in[7];
    const float* wq_svi_b = (const float*)d_in[8];
    const float* wk_w = (const float*)d_in[9];
    const float* wk_b = (const float*)d_in[10];
    const float* wv_w = (const float*)d_in[11];
    const float* wv_b = (const float*)d_in[12];
    const float* fc_w = (const float*)d_in[13];
    const float* fc_b = (const float*)d_in[14];
    float* out = (float*)d_out;

    float *Qp, *Qs, *Kh, *Vh, *c0, *c1, *madd;
    cudaGetSymbolAddress((void**)&Qp, g_Qp);
    cudaGetSymbolAddress((void**)&Qs, g_Qs);
    cudaGetSymbolAddress((void**)&Kh, g_Kh);
    cudaGetSymbolAddress((void**)&Vh, g_Vh);
    cudaGetSymbolAddress((void**)&c0, g_ctx0);
    cudaGetSymbolAddress((void**)&c1, g_ctx1);
    cudaGetSymbolAddress((void**)&madd, g_madd);

    // 0) canonicalize padding mask
    mask_expand_kernel<<<1, 1024>>>(mask, madd);

    // 1) projections -> [N,H,S,DK] (one batched launch, z = 4)
    Batch4 proj;
    proj.A[0] = Qpoi;     proj.W[0] = wq_poi_w; proj.bias[0] = wq_poi_b; proj.out[0] = Qp;
    proj.A[1] = Qsvi;     proj.W[1] = wq_svi_w; proj.bias[1] = wq_svi_b; proj.out[1] = Qs;
    proj.A[2] = Kin;      proj.W[2] = wk_w;     proj.bias[2] = wk_b;     proj.out[2] = Kh;
    proj.A[3] = Vin;      proj.W[3] = wv_w;     proj.bias[3] = wv_b;     proj.out[3] = Vh;
    gemm_tc<0><<<dim3(DDIM / 128, (SDIM * NB) / 128, 4), 256>>>(proj);

    // 2) attention (tensor cores, tf32; both streams in z)
    const int smem = (AKT * KS_STR + AKT * VS_STR + AQT * PS_STR + AKT) * (int)sizeof(float);
    cudaFuncSetAttribute((const void*)attn_tc,
                         cudaFuncAttributeMaxDynamicSharedMemorySize, smem);
    attn_tc<<<dim3(SDIM / AQT, NB * HH, 2), 128, smem>>>(Qp, Qs, Kh, Vh, madd, c0, c1);

    // 3) output FC -> [S,N,D] (one batched launch, z = 2)
    Batch4 fc;
    fc.A[0] = c0; fc.W[0] = fc_w; fc.bias[0] = fc_b; fc.out[0] = out;
    fc.A[1] = c1; fc.W[1] = fc_w; fc.bias[1] = fc_b; fc.out[1] = out + (size_t)SDIM * NB * DDIM;
    fc.A[2] = c0; fc.W[2] = fc_w; fc.bias[2] = fc_b; fc.out[2] = out;  // unused
    fc.A[3] = c1; fc.W[3] = fc_w; fc.bias[3] = fc_b; fc.out[3] = out + (size_t)SDIM * NB * DDIM;  // unused
    gemm_tc<1><<<dim3(DDIM / 128, (SDIM * NB) / 128, 2), 256>>>(fc);
}

// round 8
// speedup vs baseline: 1.6089x; 1.0342x over previous
#include <cuda_runtime.h>
#include <cstdint>

// Problem dims
#define SDIM 1024
#define NB   8
#define DDIM 1024
#define HH   16
#define DKH  64

// ---------------- scratch (device globals; no allocations allowed) ----------
__device__ float g_Qp[(size_t)NB * HH * SDIM * DKH];   // [N,H,S,DK] (tf32-rounded)
__device__ float g_Qs[(size_t)NB * HH * SDIM * DKH];
__device__ float g_Kh[(size_t)NB * HH * SDIM * DKH];
__device__ float g_Vh[(size_t)NB * HH * SDIM * DKH];
__device__ float g_ctx0[(size_t)NB * SDIM * DDIM];     // [N,S,D] (tf32-rounded)
__device__ float g_ctx1[(size_t)NB * SDIM * DDIM];
__device__ float g_madd[(size_t)NB * SDIM];            // 0 or -1e9 additive mask
__device__ float g_wt[5][(size_t)DDIM * DDIM];         // tf32-rounded weights

// ---------------- mask canonicalization -------------------------------------
__global__ void mask_expand_kernel(const unsigned char* __restrict__ m,
                                   float* __restrict__ madd)
{
    __shared__ int s_big, s_nonmult4, s_anynz;
    const int t = threadIdx.x;               // 1024 threads, single block
    if (t == 0) { s_big = 0; s_nonmult4 = 0; s_anynz = 0; }
    __syncthreads();

    const int total = NB * SDIM;             // 8192 entries
    int big = 0, nonm4 = 0, anynz = 0;
    for (int i = t; i < total; i += 1024) {
        unsigned char b = m[i];
        if (b > 1) big = 1;
        if (b) { anynz = 1; if (i & 3) nonm4 = 1; }
    }
    if (big)   atomicOr(&s_big, 1);
    if (nonm4) atomicOr(&s_nonmult4, 1);
    if (anynz) atomicOr(&s_anynz, 1);
    __syncthreads();

    const bool width4 = s_big || !s_nonmult4 || !s_anynz;

    for (int i = t; i < total; i += 1024) {
        unsigned char v;
        if (width4) {
            v = (unsigned char)(m[4 * i] | m[4 * i + 1] | m[4 * i + 2] | m[4 * i + 3]);
        } else {
            v = m[i];
        }
        madd[i] = v ? -1e9f : 0.f;
    }
}

// ---------------- tf32 helpers ----------------------------------------------
__device__ __forceinline__ float to_tf32(float x) {
    float r;
    asm("cvt.rna.tf32.f32 %0, %1;" : "=f"(r) : "f"(x));
    return r;
}

__device__ __forceinline__ void mma_tf32_16x8x8(float* c, const uint32_t* a,
                                                const uint32_t* b)
{
    asm volatile(
        "mma.sync.aligned.m16n8k8.row.col.f32.tf32.tf32.f32 "
        "{%0,%1,%2,%3}, {%4,%5,%6,%7}, {%8,%9}, {%0,%1,%2,%3};"
        : "+f"(c[0]), "+f"(c[1]), "+f"(c[2]), "+f"(c[3])
        : "r"(a[0]), "r"(a[1]), "r"(a[2]), "r"(a[3]), "r"(b[0]), "r"(b[1]));
}

__device__ __forceinline__ void cp16(void* smem, const void* gmem) {
    uint32_t s = (uint32_t)__cvta_generic_to_shared(smem);
    asm volatile("cp.async.ca.shared.global [%0], [%1], 16;" :: "r"(s), "l"(gmem));
}

// ---------------- weight pre-rounding ----------------------------------------
struct W5 { const float4* src[5]; float4* dst[5]; };
__global__ void wcvt_kernel(W5 w)
{
    const int z = blockIdx.z;
    const float4* __restrict__ s = w.src[z];
    float4* __restrict__ d = w.dst[z];
    const int i = blockIdx.x * blockDim.x + threadIdx.x;   // 262144 float4
    float4 v = s[i];
    v.x = to_tf32(v.x); v.y = to_tf32(v.y);
    v.z = to_tf32(v.z); v.w = to_tf32(v.w);
    d[i] = v;
}

// k-permuted smem slab layout (16 k per row, 16 floats per row):
//   logical pos  p = (k%4)*4 + k/4; physical = p ^ (((row>>1)&3)<<2).
template <bool CVT>
__device__ __forceinline__ void store_slab(float* stage, int row, int c4i, float4 v)
{
    const int swz = ((row >> 1) & 3) << 2;
    float* p = stage + row * 16;
    if (CVT) {
        p[(c4i      ) ^ swz] = to_tf32(v.x);
        p[(c4i +  4) ^ swz] = to_tf32(v.y);
        p[(c4i +  8) ^ swz] = to_tf32(v.z);
        p[(c4i + 12) ^ swz] = to_tf32(v.w);
    } else {
        p[(c4i      ) ^ swz] = v.x;
        p[(c4i +  4) ^ swz] = v.y;
        p[(c4i +  8) ^ swz] = v.z;
        p[(c4i + 12) ^ swz] = v.w;
    }
}

// ---------------- batched, pipelined tensor-core GEMM -----------------------
// MODE 0: A raw fp32 (cvt on store); W pre-rounded; epilogue writes tf32-rounded.
// MODE 1: A pre-rounded (ctx); W pre-rounded; epilogue raw (final output).
struct Batch4 {
    const float* A[4];
    const float* W[4];
    const float* bias[4];
    float* out[4];
};

template <int MODE>
__global__ void __launch_bounds__(256, 2)
gemm_tc(Batch4 batch)
{
    constexpr int BM = 128, BN = 128, BK = 16, KD = 1024;
    __shared__ float As[2][BM * 16];
    __shared__ float Bs[2][BN * 16];

    const int z = blockIdx.z;
    const float* __restrict__ A    = batch.A[z];
    const float* __restrict__ W    = batch.W[z];
    const float* __restrict__ bias = batch.bias[z];
    float* __restrict__ out        = batch.out[z];

    const int tid  = threadIdx.x;
    const int wid  = tid >> 5;
    const int lane = tid & 31;
    const int wm = wid & 1;
    const int wn = wid >> 1;
    const int m0 = blockIdx.y * BM;
    const int n0 = blockIdx.x * BN;

    const int r  = lane >> 2;
    const int cq = lane & 3;
    const int cqo = cq * 4;

    const int lrow0 = tid >> 2;               // 0..63
    const int lrow1 = lrow0 + 64;             // 64..127
    const int c4i   = tid & 3;
    const int lc4   = c4i << 2;

    const float* Aptr = A + (size_t)m0 * KD;
    const float* Wptr = W + (size_t)n0 * KD;

    float acc[4][4][4];
    #pragma unroll
    for (int mt = 0; mt < 4; mt++)
        #pragma unroll
        for (int nt = 0; nt < 4; nt++)
            #pragma unroll
            for (int i = 0; i < 4; i++) acc[mt][nt][i] = 0.f;

    float4 pa0, pa1, pb0, pb1;

    pa0 = *(const float4*)(Aptr + (size_t)lrow0 * KD + lc4);
    pa1 = *(const float4*)(Aptr + (size_t)lrow1 * KD + lc4);
    pb0 = *(const float4*)(Wptr + (size_t)lrow0 * KD + lc4);
    pb1 = *(const float4*)(Wptr + (size_t)lrow1 * KD + lc4);
    store_slab<MODE == 0>(As[0], lrow0, c4i, pa0);
    store_slab<MODE == 0>(As[0], lrow1, c4i, pa1);
    store_slab<false>(Bs[0], lrow0, c4i, pb0);
    store_slab<false>(Bs[0], lrow1, c4i, pb1);
    __syncthreads();

    for (int it = 0; it < KD / BK; it++) {
        const int cur = it & 1;
        const int nxt = cur ^ 1;
        const bool more = (it + 1) < KD / BK;

        if (more) {
            const int kn = (it + 1) * BK;
            pa0 = *(const float4*)(Aptr + (size_t)lrow0 * KD + kn + lc4);
            pa1 = *(const float4*)(Aptr + (size_t)lrow1 * KD + kn + lc4);
            pb0 = *(const float4*)(Wptr + (size_t)lrow0 * KD + kn + lc4);
            pb1 = *(const float4*)(Wptr + (size_t)lrow1 * KD + kn + lc4);
        }

        const float* Asc = As[cur];
        const float* Bsc = Bs[cur];

        uint32_t bf0[4][2], bf1[4][2];
        #pragma unroll
        for (int nt = 0; nt < 4; nt++) {
            const int nrow = wn * 32 + nt * 8 + r;
            const int swz = ((nrow >> 1) & 3) << 2;
            const float4 bl = *(const float4*)(Bsc + nrow * 16 + (cqo ^ swz));
            bf0[nt][0] = __float_as_uint(bl.x);
            bf0[nt][1] = __float_as_uint(bl.y);
            bf1[nt][0] = __float_as_uint(bl.z);
            bf1[nt][1] = __float_as_uint(bl.w);
        }

        #pragma unroll
        for (int mt = 0; mt < 4; mt++) {
            const int mr = wm * 64 + mt * 16 + r;
            const int swz = ((mr >> 1) & 3) << 2;
            const float4 lf0 = *(const float4*)(Asc + mr * 16 + (cqo ^ swz));
            const float4 lf8 = *(const float4*)(Asc + (mr + 8) * 16 + (cqo ^ swz));

            uint32_t a0[4], a1[4];
            a0[0] = __float_as_uint(lf0.x); a0[1] = __float_as_uint(lf8.x);
            a0[2] = __float_as_uint(lf0.y); a0[3] = __float_as_uint(lf8.y);
            a1[0] = __float_as_uint(lf0.z); a1[1] = __float_as_uint(lf8.z);
            a1[2] = __float_as_uint(lf0.w); a1[3] = __float_as_uint(lf8.w);

            #pragma unroll
            for (int nt = 0; nt < 4; nt++)
                mma_tf32_16x8x8(acc[mt][nt], a0, bf0[nt]);
            #pragma unroll
            for (int nt = 0; nt < 4; nt++)
                mma_tf32_16x8x8(acc[mt][nt], a1, bf1[nt]);
        }

        if (more) {
            store_slab<MODE == 0>(As[nxt], lrow0, c4i, pa0);
            store_slab<MODE == 0>(As[nxt], lrow1, c4i, pa1);
            store_slab<false>(Bs[nxt], lrow0, c4i, pb0);
            store_slab<false>(Bs[nxt], lrow1, c4i, pb1);
        }
        __syncthreads();
    }

    // ---- epilogue: bias + scatter; MODE 0 writes tf32-rounded ----
    const int cpair = (lane & 3) * 2;
    #pragma unroll
    for (int nt = 0; nt < 4; nt++) {
        const int dout = n0 + wn * 32 + nt * 8 + cpair;
        const float2 bb = *(const float2*)(bias + dout);
        #pragma unroll
        for (int mt = 0; mt < 4; mt++) {
            #pragma unroll
            for (int half = 0; half < 2; half++) {
                const int m = m0 + wm * 64 + mt * 16 + r + half * 8;
                float2 v;
                v.x = acc[mt][nt][half * 2 + 0] + bb.x;
                v.y = acc[mt][nt][half * 2 + 1] + bb.y;
                if (MODE == 0) {
                    v.x = to_tf32(v.x);
                    v.y = to_tf32(v.y);
                    const int s = m >> 3, n = m & 7;
                    const int h = dout >> 6, dk = dout & 63;
                    *(float2*)(out + ((size_t)((n * HH + h) * SDIM + s)) * DKH + dk) = v;
                } else {
                    const int n = m >> 10, s = m & 1023;
                    *(float2*)(out + ((size_t)(s * NB + n)) * DDIM + dout) = v;
                }
            }
        }
    }
}

// ---------------- tensor-core flash attention --------------------------------
// 256 threads, 8 warps; 128 q rows per block (warp w owns rows w*16..+15).
// Q/K/V already tf32-rounded by the projection epilogue -> raw loads.
#define AQT 128
#define AKT 64
#define KS_STR 68
#define VS_STR 72
#define PS_STR 68

__global__ void __launch_bounds__(256, 2)
attn_tc(const float* __restrict__ Qp, const float* __restrict__ Qsv,
        const float* __restrict__ Kh, const float* __restrict__ Vh,
        const float* __restrict__ maddg,
        float* __restrict__ ctx0, float* __restrict__ ctx1)
{
    extern __shared__ float sm[];
    float* Ks   = sm;                         // [64][KS_STR]
    float* Vs   = Ks + AKT * KS_STR;          // [64][VS_STR]
    float* Ps   = Vs + AKT * VS_STR;          // [128][PS_STR]
    float* madd = Ps + AQT * PS_STR;          // [64]

    const int nh = blockIdx.y;
    const int n  = nh / HH;
    const int stream = blockIdx.z;
    const int q0 = blockIdx.x * AQT;
    const int tid = threadIdx.x;
    const int wid = tid >> 5;
    const int lane = tid & 31;
    const int r  = lane >> 2;
    const int cq = lane & 3;

    const float* Qb = (stream ? Qsv : Qp) + (size_t)nh * SDIM * DKH;
    const float* Kb = Kh + (size_t)nh * SDIM * DKH;
    const float* Vb = Vh + (size_t)nh * SDIM * DKH;

    // Q fragments (pre-rounded -> raw loads)
    uint32_t qf[8][4];
    {
        const float* q0p = Qb + (size_t)(q0 + wid * 16 + r) * DKH;
        const float* q8p = q0p + 8 * DKH;
        #pragma unroll
        for (int ks = 0; ks < 8; ks++) {
            qf[ks][0] = __float_as_uint(q0p[ks * 8 + cq]);
            qf[ks][1] = __float_as_uint(q8p[ks * 8 + cq]);
            qf[ks][2] = __float_as_uint(q0p[ks * 8 + cq + 4]);
            qf[ks][3] = __float_as_uint(q8p[ks * 8 + cq + 4]);
        }
    }

    float o[8][4];
    #pragma unroll
    for (int nt = 0; nt < 8; nt++)
        #pragma unroll
        for (int i = 0; i < 4; i++) o[nt][i] = 0.f;
    float m0v = -1e30f, m1v = -1e30f, l0 = 0.f, l1 = 0.f;

    for (int kt = 0; kt < SDIM / AKT; kt++) {
        const int k0 = kt * AKT;
        // ---- K/V tiles via cp.async (raw, pre-rounded) ----
        {
            const float* ksrc = Kb + (size_t)k0 * DKH;
            const float* vsrc = Vb + (size_t)k0 * DKH;
            #pragma unroll
            for (int i = 0; i < 4; i++) {
                const int idx = tid + 256 * i;     // 0..1023
                const int row = idx >> 4;
                const int c4  = (idx & 15) << 2;
                cp16(Ks + row * KS_STR + c4, ksrc + idx * 4);
                cp16(Vs + row * VS_STR + c4, vsrc + idx * 4);
            }
            if (tid < AKT) madd[tid] = maddg[n * SDIM + k0 + tid];
            asm volatile("cp.async.wait_all;" ::: "memory");
        }
        __syncthreads();

        // ---- scores: S = Q @ K^T ----
        float sc[8][4];
        #pragma unroll
        for (int nt = 0; nt < 8; nt++)
            #pragma unroll
            for (int i = 0; i < 4; i++) sc[nt][i] = 0.f;

        #pragma unroll
        for (int ks = 0; ks < 8; ks++) {
            const int kb = ks * 8;
            #pragma unroll
            for (int nt = 0; nt < 8; nt++) {
                uint32_t b[2];
                const float* p = Ks + (nt * 8 + r) * KS_STR + kb + cq;
                b[0] = __float_as_uint(p[0]);
                b[1] = __float_as_uint(p[4]);
                mma_tf32_16x8x8(sc[nt], qf[ks], b);
            }
        }

        // ---- online softmax ----
        float tmax0 = -1e30f, tmax1 = -1e30f;
        #pragma unroll
        for (int nt = 0; nt < 8; nt++) {
            const int j = nt * 8 + 2 * cq;
            const float ma = madd[j], mb = madd[j + 1];
            sc[nt][0] = sc[nt][0] * 0.125f + ma;
            sc[nt][1] = sc[nt][1] * 0.125f + mb;
            sc[nt][2] = sc[nt][2] * 0.125f + ma;
            sc[nt][3] = sc[nt][3] * 0.125f + mb;
            tmax0 = fmaxf(tmax0, fmaxf(sc[nt][0], sc[nt][1]));
            tmax1 = fmaxf(tmax1, fmaxf(sc[nt][2], sc[nt][3]));
        }
        tmax0 = fmaxf(tmax0, __shfl_xor_sync(0xffffffffu, tmax0, 1));
        tmax0 = fmaxf(tmax0, __shfl_xor_sync(0xffffffffu, tmax0, 2));
        tmax1 = fmaxf(tmax1, __shfl_xor_sync(0xffffffffu, tmax1, 1));
        tmax1 = fmaxf(tmax1, __shfl_xor_sync(0xffffffffu, tmax1, 2));

        const float mn0 = fmaxf(m0v, tmax0);
        const float mn1 = fmaxf(m1v, tmax1);
        const float cr0 = __expf(m0v - mn0);
        const float cr1 = __expf(m1v - mn1);
        m0v = mn0; m1v = mn1;

        float ls0 = 0.f, ls1 = 0.f;
        float* prow0 = Ps + (wid * 16 + r) * PS_STR + 2 * cq;
        float* prow8 = prow0 + 8 * PS_STR;
        #pragma unroll
        for (int nt = 0; nt < 8; nt++) {
            const float p0 = __expf(sc[nt][0] - mn0);
            const float p1 = __expf(sc[nt][1] - mn0);
            const float p2 = __expf(sc[nt][2] - mn1);
            const float p3 = __expf(sc[nt][3] - mn1);
            ls0 += p0 + p1;
            ls1 += p2 + p3;
            float2 w0, w1;
            w0.x = to_tf32(p0); w0.y = to_tf32(p1);
            w1.x = to_tf32(p2); w1.y = to_tf32(p3);
            *(float2*)(prow0 + nt * 8) = w0;
            *(float2*)(prow8 + nt * 8) = w1;
            o[nt][0] *= cr0; o[nt][1] *= cr0;
            o[nt][2] *= cr1; o[nt][3] *= cr1;
        }
        ls0 += __shfl_xor_sync(0xffffffffu, ls0, 1);
        ls0 += __shfl_xor_sync(0xffffffffu, ls0, 2);
        ls1 += __shfl_xor_sync(0xffffffffu, ls1, 1);
        ls1 += __shfl_xor_sync(0xffffffffu, ls1, 2);
        l0 = l0 * cr0 + ls0;
        l1 = l1 * cr1 + ls1;

        __syncwarp();

        // ---- O += P @ V ----
        #pragma unroll
        for (int ks = 0; ks < 8; ks++) {
            const int kb = ks * 8;
            uint32_t a[4];
            const float* pa = Ps + (wid * 16 + r) * PS_STR + kb;
            a[0] = __float_as_uint(pa[cq]);
            a[1] = __float_as_uint(pa[8 * PS_STR + cq]);
            a[2] = __float_as_uint(pa[cq + 4]);
            a[3] = __float_as_uint(pa[8 * PS_STR + cq + 4]);
            #pragma unroll
            for (int nt = 0; nt < 8; nt++) {
                uint32_t b[2];
                const float* pv = Vs + (kb + cq) * VS_STR + nt * 8 + r;
                b[0] = __float_as_uint(pv[0]);
                b[1] = __float_as_uint(pv[4 * VS_STR]);
                mma_tf32_16x8x8(o[nt], a, b);
            }
        }
        __syncthreads();
    }

    // ---- epilogue: write tf32-rounded ctx (consumed by FC gemm) ----
    const float inv0 = 1.f / l0;
    const float inv1 = 1.f / l1;
    const int h = nh % HH;
    const int q = q0 + wid * 16 + r;
    float* outp = (stream ? ctx1 : ctx0)
                + ((size_t)(n * SDIM + q)) * DDIM + h * DKH;
    float* outp8 = outp + 8 * DDIM;
    #pragma unroll
    for (int nt = 0; nt < 8; nt++) {
        const int dk = nt * 8 + 2 * cq;
        float2 v0, v1;
        v0.x = to_tf32(o[nt][0] * inv0); v0.y = to_tf32(o[nt][1] * inv0);
        v1.x = to_tf32(o[nt][2] * inv1); v1.y = to_tf32(o[nt][3] * inv1);
        *(float2*)(outp  + dk) = v0;
        *(float2*)(outp8 + dk) = v1;
    }
}

// ---------------------------------------------------------------------------
extern "C" void kernel_launch(void* const* d_in, const int* in_sizes, int n_in,
                              void* d_out, int out_size)
{
    const float* Qpoi = (const float*)d_in[0];
    const float* Qsvi = (const float*)d_in[1];
    const float* Kin  = (const float*)d_in[2];
    const float* Vin  = (const float*)d_in[3];
    const unsigned char* mask = (const unsigned char*)d_in[4];
    const float* wq_poi_w = (const float*)d_in[5];
    const float* wq_poi_b = (const float*)d_in[6];
    const float* wq_svi_w = (const float*)d_in[7];
    const float* wq_svi_b = (const float*)d_in[8];
    const float* wk_w = (const float*)d_in[9];
    const float* wk_b = (const float*)d_in[10];
    const float* wv_w = (const float*)d_in[11];
    const float* wv_b = (const float*)d_in[12];
    const float* fc_w = (const float*)d_in[13];
    const float* fc_b = (const float*)d_in[14];
    float* out = (float*)d_out;

    float *Qp, *Qs, *Kh, *Vh, *c0, *c1, *madd, *wt;
    cudaGetSymbolAddress((void**)&Qp, g_Qp);
    cudaGetSymbolAddress((void**)&Qs, g_Qs);
    cudaGetSymbolAddress((void**)&Kh, g_Kh);
    cudaGetSymbolAddress((void**)&Vh, g_Vh);
    cudaGetSymbolAddress((void**)&c0, g_ctx0);
    cudaGetSymbolAddress((void**)&c1, g_ctx1);
    cudaGetSymbolAddress((void**)&madd, g_madd);
    cudaGetSymbolAddress((void**)&wt, g_wt);

    float* wt_q_poi = wt + 0 * (size_t)DDIM * DDIM;
    float* wt_q_svi = wt + 1 * (size_t)DDIM * DDIM;
    float* wt_k     = wt + 2 * (size_t)DDIM * DDIM;
    float* wt_v     = wt + 3 * (size_t)DDIM * DDIM;
    float* wt_fc    = wt + 4 * (size_t)DDIM * DDIM;

    // 0a) canonicalize padding mask
    mask_expand_kernel<<<1, 1024>>>(mask, madd);

    // 0b) pre-round the 5 weight matrices to tf32
    W5 w5;
    w5.src[0] = (const float4*)wq_poi_w; w5.dst[0] = (float4*)wt_q_poi;
    w5.src[1] = (const float4*)wq_svi_w; w5.dst[1] = (float4*)wt_q_svi;
    w5.src[2] = (const float4*)wk_w;     w5.dst[2] = (float4*)wt_k;
    w5.src[3] = (const float4*)wv_w;     w5.dst[3] = (float4*)wt_v;
    w5.src[4] = (const float4*)fc_w;     w5.dst[4] = (float4*)wt_fc;
    wcvt_kernel<<<dim3(DDIM * DDIM / 4 / 256, 1, 5), 256>>>(w5);

    // 1) projections -> [N,H,S,DK] (one batched launch, z = 4)
    Batch4 proj;
    proj.A[0] = Qpoi; proj.W[0] = wt_q_poi; proj.bias[0] = wq_poi_b; proj.out[0] = Qp;
    proj.A[1] = Qsvi; proj.W[1] = wt_q_svi; proj.bias[1] = wq_svi_b; proj.out[1] = Qs;
    proj.A[2] = Kin;  proj.W[2] = wt_k;     proj.bias[2] = wk_b;     proj.out[2] = Kh;
    proj.A[3] = Vin;  proj.W[3] = wt_v;     proj.bias[3] = wv_b;     proj.out[3] = Vh;
    gemm_tc<0><<<dim3(DDIM / 128, (SDIM * NB) / 128, 4), 256>>>(proj);

    // 2) attention (tensor cores, tf32; both streams in z)
    const int smem = (AKT * KS_STR + AKT * VS_STR + AQT * PS_STR + AKT) * (int)sizeof(float);
    cudaFuncSetAttribute((const void*)attn_tc,
                         cudaFuncAttributeMaxDynamicSharedMemorySize, smem);
    attn_tc<<<dim3(SDIM / AQT, NB * HH, 2), 256, smem>>>(Qp, Qs, Kh, Vh, madd, c0, c1);

    // 3) output FC -> [S,N,D] (one batched launch, z = 2)
    Batch4 fc;
    fc.A[0] = c0; fc.W[0] = wt_fc; fc.bias[0] = fc_b; fc.out[0] = out;
    fc.A[1] = c1; fc.W[1] = wt_fc; fc.bias[1] = fc_b; fc.out[1] = out + (size_t)SDIM * NB * DDIM;
    fc.A[2] = c0; fc.W[2] = wt_fc; fc.bias[2] = fc_b; fc.out[2] = out;  // unused
    fc.A[3] = c1; fc.W[3] = wt_fc; fc.bias[3] = fc_b; fc.out[3] = out + (size_t)SDIM * NB * DDIM;  // unused
    gemm_tc<1><<<dim3(DDIM / 128, (SDIM * NB) / 128, 2), 256>>>(fc);
}

// round 9
// speedup vs baseline: 1.6814x; 1.0451x over previous
#include <cuda_runtime.h>
#include <cstdint>

// Problem dims
#define SDIM 1024
#define NB   8
#define DDIM 1024
#define HH   16
#define DKH  64

// ---------------- scratch (device globals; no allocations allowed) ----------
__device__ float g_Qp[(size_t)NB * HH * SDIM * DKH];   // [N,H,S,DK] (tf32-rounded)
__device__ float g_Qs[(size_t)NB * HH * SDIM * DKH];
__device__ float g_Kh[(size_t)NB * HH * SDIM * DKH];
__device__ float g_Vh[(size_t)NB * HH * SDIM * DKH];
__device__ float g_ctx0[(size_t)NB * SDIM * DDIM];     // [N,S,D] (tf32-rounded)
__device__ float g_ctx1[(size_t)NB * SDIM * DDIM];
__device__ float g_madd[(size_t)NB * SDIM];            // 0 or -1e9 additive mask
__device__ float g_wt[5][(size_t)DDIM * DDIM];         // tf32-rounded weights

// ---------------- mask canonicalization -------------------------------------
__global__ void mask_expand_kernel(const unsigned char* __restrict__ m,
                                   float* __restrict__ madd)
{
    __shared__ int s_big, s_nonmult4, s_anynz;
    const int t = threadIdx.x;               // 1024 threads, single block
    if (t == 0) { s_big = 0; s_nonmult4 = 0; s_anynz = 0; }
    __syncthreads();

    const int total = NB * SDIM;             // 8192 entries
    int big = 0, nonm4 = 0, anynz = 0;
    for (int i = t; i < total; i += 1024) {
        unsigned char b = m[i];
        if (b > 1) big = 1;
        if (b) { anynz = 1; if (i & 3) nonm4 = 1; }
    }
    if (big)   atomicOr(&s_big, 1);
    if (nonm4) atomicOr(&s_nonmult4, 1);
    if (anynz) atomicOr(&s_anynz, 1);
    __syncthreads();

    const bool width4 = s_big || !s_nonmult4 || !s_anynz;

    for (int i = t; i < total; i += 1024) {
        unsigned char v;
        if (width4) {
            v = (unsigned char)(m[4 * i] | m[4 * i + 1] | m[4 * i + 2] | m[4 * i + 3]);
        } else {
            v = m[i];
        }
        madd[i] = v ? -1e9f : 0.f;
    }
}

// ---------------- tf32 helpers ----------------------------------------------
__device__ __forceinline__ float to_tf32(float x) {
    float r;
    asm("cvt.rna.tf32.f32 %0, %1;" : "=f"(r) : "f"(x));
    return r;
}

__device__ __forceinline__ void mma_tf32_16x8x8(float* c, const uint32_t* a,
                                                const uint32_t* b)
{
    asm volatile(
        "mma.sync.aligned.m16n8k8.row.col.f32.tf32.tf32.f32 "
        "{%0,%1,%2,%3}, {%4,%5,%6,%7}, {%8,%9}, {%0,%1,%2,%3};"
        : "+f"(c[0]), "+f"(c[1]), "+f"(c[2]), "+f"(c[3])
        : "r"(a[0]), "r"(a[1]), "r"(a[2]), "r"(a[3]), "r"(b[0]), "r"(b[1]));
}

__device__ __forceinline__ void cp16(void* smem, const void* gmem) {
    uint32_t s = (uint32_t)__cvta_generic_to_shared(smem);
    asm volatile("cp.async.ca.shared.global [%0], [%1], 16;" :: "r"(s), "l"(gmem));
}

// ---------------- weight pre-rounding ----------------------------------------
struct W5 { const float4* src[5]; float4* dst[5]; };
__global__ void wcvt_kernel(W5 w)
{
    const int z = blockIdx.z;
    const float4* __restrict__ s = w.src[z];
    float4* __restrict__ d = w.dst[z];
    const int i = blockIdx.x * blockDim.x + threadIdx.x;   // 262144 float4
    float4 v = s[i];
    v.x = to_tf32(v.x); v.y = to_tf32(v.y);
    v.z = to_tf32(v.z); v.w = to_tf32(v.w);
    d[i] = v;
}

// k-permuted smem slab layout (16 k per row, 16 floats per row):
//   logical pos  p = (k%4)*4 + k/4; physical = p ^ (((row>>1)&3)<<2).
template <bool CVT>
__device__ __forceinline__ void store_slab(float* stage, int row, int c4i, float4 v)
{
    const int swz = ((row >> 1) & 3) << 2;
    float* p = stage + row * 16;
    if (CVT) {
        p[(c4i      ) ^ swz] = to_tf32(v.x);
        p[(c4i +  4) ^ swz] = to_tf32(v.y);
        p[(c4i +  8) ^ swz] = to_tf32(v.z);
        p[(c4i + 12) ^ swz] = to_tf32(v.w);
    } else {
        p[(c4i      ) ^ swz] = v.x;
        p[(c4i +  4) ^ swz] = v.y;
        p[(c4i +  8) ^ swz] = v.z;
        p[(c4i + 12) ^ swz] = v.w;
    }
}

// ---------------- batched, pipelined tensor-core GEMM -----------------------
struct Batch4 {
    const float* A[4];
    const float* W[4];
    const float* bias[4];
    float* out[4];
};

template <int MODE>
__global__ void __launch_bounds__(256, 2)
gemm_tc(Batch4 batch)
{
    constexpr int BM = 128, BN = 128, BK = 16, KD = 1024;
    __shared__ float As[2][BM * 16];
    __shared__ float Bs[2][BN * 16];

    const int z = blockIdx.z;
    const float* __restrict__ A    = batch.A[z];
    const float* __restrict__ W    = batch.W[z];
    const float* __restrict__ bias = batch.bias[z];
    float* __restrict__ out        = batch.out[z];

    const int tid  = threadIdx.x;
    const int wid  = tid >> 5;
    const int lane = tid & 31;
    const int wm = wid & 1;
    const int wn = wid >> 1;
    const int m0 = blockIdx.y * BM;
    const int n0 = blockIdx.x * BN;

    const int r  = lane >> 2;
    const int cq = lane & 3;
    const int cqo = cq * 4;

    const int lrow0 = tid >> 2;               // 0..63
    const int lrow1 = lrow0 + 64;             // 64..127
    const int c4i   = tid & 3;
    const int lc4   = c4i << 2;

    const float* Aptr = A + (size_t)m0 * KD;
    const float* Wptr = W + (size_t)n0 * KD;

    float acc[4][4][4];
    #pragma unroll
    for (int mt = 0; mt < 4; mt++)
        #pragma unroll
        for (int nt = 0; nt < 4; nt++)
            #pragma unroll
            for (int i = 0; i < 4; i++) acc[mt][nt][i] = 0.f;

    float4 pa0, pa1, pb0, pb1;

    pa0 = *(const float4*)(Aptr + (size_t)lrow0 * KD + lc4);
    pa1 = *(const float4*)(Aptr + (size_t)lrow1 * KD + lc4);
    pb0 = *(const float4*)(Wptr + (size_t)lrow0 * KD + lc4);
    pb1 = *(const float4*)(Wptr + (size_t)lrow1 * KD + lc4);
    store_slab<MODE == 0>(As[0], lrow0, c4i, pa0);
    store_slab<MODE == 0>(As[0], lrow1, c4i, pa1);
    store_slab<false>(Bs[0], lrow0, c4i, pb0);
    store_slab<false>(Bs[0], lrow1, c4i, pb1);
    __syncthreads();

    for (int it = 0; it < KD / BK; it++) {
        const int cur = it & 1;
        const int nxt = cur ^ 1;
        const bool more = (it + 1) < KD / BK;

        if (more) {
            const int kn = (it + 1) * BK;
            pa0 = *(const float4*)(Aptr + (size_t)lrow0 * KD + kn + lc4);
            pa1 = *(const float4*)(Aptr + (size_t)lrow1 * KD + kn + lc4);
            pb0 = *(const float4*)(Wptr + (size_t)lrow0 * KD + kn + lc4);
            pb1 = *(const float4*)(Wptr + (size_t)lrow1 * KD + kn + lc4);
        }

        const float* Asc = As[cur];
        const float* Bsc = Bs[cur];

        uint32_t bf0[4][2], bf1[4][2];
        #pragma unroll
        for (int nt = 0; nt < 4; nt++) {
            const int nrow = wn * 32 + nt * 8 + r;
            const int swz = ((nrow >> 1) & 3) << 2;
            const float4 bl = *(const float4*)(Bsc + nrow * 16 + (cqo ^ swz));
            bf0[nt][0] = __float_as_uint(bl.x);
            bf0[nt][1] = __float_as_uint(bl.y);
            bf1[nt][0] = __float_as_uint(bl.z);
            bf1[nt][1] = __float_as_uint(bl.w);
        }

        #pragma unroll
        for (int mt = 0; mt < 4; mt++) {
            const int mr = wm * 64 + mt * 16 + r;
            const int swz = ((mr >> 1) & 3) << 2;
            const float4 lf0 = *(const float4*)(Asc + mr * 16 + (cqo ^ swz));
            const float4 lf8 = *(const float4*)(Asc + (mr + 8) * 16 + (cqo ^ swz));

            uint32_t a0[4], a1[4];
            a0[0] = __float_as_uint(lf0.x); a0[1] = __float_as_uint(lf8.x);
            a0[2] = __float_as_uint(lf0.y); a0[3] = __float_as_uint(lf8.y);
            a1[0] = __float_as_uint(lf0.z); a1[1] = __float_as_uint(lf8.z);
            a1[2] = __float_as_uint(lf0.w); a1[3] = __float_as_uint(lf8.w);

            #pragma unroll
            for (int nt = 0; nt < 4; nt++)
                mma_tf32_16x8x8(acc[mt][nt], a0, bf0[nt]);
            #pragma unroll
            for (int nt = 0; nt < 4; nt++)
                mma_tf32_16x8x8(acc[mt][nt], a1, bf1[nt]);
        }

        if (more) {
            store_slab<MODE == 0>(As[nxt], lrow0, c4i, pa0);
            store_slab<MODE == 0>(As[nxt], lrow1, c4i, pa1);
            store_slab<false>(Bs[nxt], lrow0, c4i, pb0);
            store_slab<false>(Bs[nxt], lrow1, c4i, pb1);
        }
        __syncthreads();
    }

    const int cpair = (lane & 3) * 2;
    #pragma unroll
    for (int nt = 0; nt < 4; nt++) {
        const int dout = n0 + wn * 32 + nt * 8 + cpair;
        const float2 bb = *(const float2*)(bias + dout);
        #pragma unroll
        for (int mt = 0; mt < 4; mt++) {
            #pragma unroll
            for (int half = 0; half < 2; half++) {
                const int m = m0 + wm * 64 + mt * 16 + r + half * 8;
                float2 v;
                v.x = acc[mt][nt][half * 2 + 0] + bb.x;
                v.y = acc[mt][nt][half * 2 + 1] + bb.y;
                if (MODE == 0) {
                    v.x = to_tf32(v.x);
                    v.y = to_tf32(v.y);
                    const int s = m >> 3, n = m & 7;
                    const int h = dout >> 6, dk = dout & 63;
                    *(float2*)(out + ((size_t)((n * HH + h) * SDIM + s)) * DKH + dk) = v;
                } else {
                    const int n = m >> 10, s = m & 1023;
                    *(float2*)(out + ((size_t)(s * NB + n)) * DDIM + dout) = v;
                }
            }
        }
    }
}

// ---------------- tensor-core flash attention --------------------------------
// 128 threads, 4 warps; warp w owns 32 q rows (two m16 tiles). K/V fragment
// loads shared across both m-tiles -> half the smem fragment traffic.
// Double-buffered cp.async K/V prefetch.
#define AQT 128
#define AKT 64
#define KS_STR 68
#define VS_STR 72
#define PS_STR 68
#define KSZ (AKT * KS_STR)
#define VSZ (AKT * VS_STR)

__global__ void __launch_bounds__(128, 2)
attn_tc(const float* __restrict__ Qp, const float* __restrict__ Qsv,
        const float* __restrict__ Kh, const float* __restrict__ Vh,
        const float* __restrict__ maddg,
        float* __restrict__ ctx0, float* __restrict__ ctx1)
{
    extern __shared__ float sm[];
    float* KsB   = sm;                        // [2][64][KS_STR]
    float* VsB   = KsB + 2 * KSZ;             // [2][64][VS_STR]
    float* Ps    = VsB + 2 * VSZ;             // [128][PS_STR]
    float* maddB = Ps + AQT * PS_STR;         // [2][64]

    const int nh = blockIdx.y;
    const int n  = nh / HH;
    const int stream = blockIdx.z;
    const int q0 = blockIdx.x * AQT;
    const int tid = threadIdx.x;
    const int wid = tid >> 5;                 // 0..3
    const int lane = tid & 31;
    const int r  = lane >> 2;
    const int cq = lane & 3;

    const float* Qb = (stream ? Qsv : Qp) + (size_t)nh * SDIM * DKH;
    const float* Kb = Kh + (size_t)nh * SDIM * DKH;
    const float* Vb = Vh + (size_t)nh * SDIM * DKH;
    const float* mrow = maddg + n * SDIM;

    // Q fragments for the warp's two m16 tiles (pre-rounded -> raw loads)
    uint32_t qf0[8][4], qf1[8][4];
    {
        const float* qa = Qb + (size_t)(q0 + wid * 32 + r) * DKH;
        const float* qb = qa + 8 * DKH;
        const float* qc = qa + 16 * DKH;
        const float* qd = qa + 24 * DKH;
        #pragma unroll
        for (int ks = 0; ks < 8; ks++) {
            qf0[ks][0] = __float_as_uint(qa[ks * 8 + cq]);
            qf0[ks][1] = __float_as_uint(qb[ks * 8 + cq]);
            qf0[ks][2] = __float_as_uint(qa[ks * 8 + cq + 4]);
            qf0[ks][3] = __float_as_uint(qb[ks * 8 + cq + 4]);
            qf1[ks][0] = __float_as_uint(qc[ks * 8 + cq]);
            qf1[ks][1] = __float_as_uint(qd[ks * 8 + cq]);
            qf1[ks][2] = __float_as_uint(qc[ks * 8 + cq + 4]);
            qf1[ks][3] = __float_as_uint(qd[ks * 8 + cq + 4]);
        }
    }

    float o0[8][4], o1[8][4];
    #pragma unroll
    for (int nt = 0; nt < 8; nt++)
        #pragma unroll
        for (int i = 0; i < 4; i++) { o0[nt][i] = 0.f; o1[nt][i] = 0.f; }
    float mA0 = -1e30f, mA1 = -1e30f, lA0 = 0.f, lA1 = 0.f;   // m-tile 0, rows r / r+8
    float mB0 = -1e30f, mB1 = -1e30f, lB0 = 0.f, lB1 = 0.f;   // m-tile 1

    // prologue fill: stage 0, k0 = 0
    {
        const float* ksrc = Kb;
        const float* vsrc = Vb;
        #pragma unroll
        for (int i = 0; i < 8; i++) {
            const int idx = tid + 128 * i;         // 0..1023
            const int row = idx >> 4;
            const int c4  = (idx & 15) << 2;
            cp16(KsB + row * KS_STR + c4, ksrc + idx * 4);
            cp16(VsB + row * VS_STR + c4, vsrc + idx * 4);
        }
        if (tid < AKT) maddB[tid] = mrow[tid];
        asm volatile("cp.async.wait_all;" ::: "memory");
    }
    __syncthreads();

    for (int kt = 0; kt < SDIM / AKT; kt++) {
        const int cur = kt & 1;
        const bool more = (kt + 1) < SDIM / AKT;

        // prefetch next K/V tile into the other stage (waited at loop end)
        if (more) {
            const int kn = (kt + 1) * AKT;
            const float* ksrc = Kb + (size_t)kn * DKH;
            const float* vsrc = Vb + (size_t)kn * DKH;
            float* kd = KsB + (cur ^ 1) * KSZ;
            float* vd = VsB + (cur ^ 1) * VSZ;
            #pragma unroll
            for (int i = 0; i < 8; i++) {
                const int idx = tid + 128 * i;
                const int row = idx >> 4;
                const int c4  = (idx & 15) << 2;
                cp16(kd + row * KS_STR + c4, ksrc + idx * 4);
                cp16(vd + row * VS_STR + c4, vsrc + idx * 4);
            }
            if (tid < AKT) maddB[(cur ^ 1) * AKT + tid] = mrow[kn + tid];
        }

        const float* Kst = KsB + cur * KSZ;
        const float* Vst = VsB + cur * VSZ;
        const float* madd = maddB + cur * AKT;

        // ---- scores for both m-tiles; each K fragment feeds 2 MMAs ----
        float sc0[8][4], sc1[8][4];
        #pragma unroll
        for (int nt = 0; nt < 8; nt++)
            #pragma unroll
            for (int i = 0; i < 4; i++) { sc0[nt][i] = 0.f; sc1[nt][i] = 0.f; }

        #pragma unroll
        for (int ks = 0; ks < 8; ks++) {
            const int kb = ks * 8;
            #pragma unroll
            for (int nt = 0; nt < 8; nt++) {
                uint32_t b[2];
                const float* p = Kst + (nt * 8 + r) * KS_STR + kb + cq;
                b[0] = __float_as_uint(p[0]);
                b[1] = __float_as_uint(p[4]);
                mma_tf32_16x8x8(sc0[nt], qf0[ks], b);
                mma_tf32_16x8x8(sc1[nt], qf1[ks], b);
            }
        }

        // ---- online softmax, m-tile 0 ----
        {
            float tmax0 = -1e30f, tmax1 = -1e30f;
            #pragma unroll
            for (int nt = 0; nt < 8; nt++) {
                const int j = nt * 8 + 2 * cq;
                const float ma = madd[j], mb = madd[j + 1];
                sc0[nt][0] = sc0[nt][0] * 0.125f + ma;
                sc0[nt][1] = sc0[nt][1] * 0.125f + mb;
                sc0[nt][2] = sc0[nt][2] * 0.125f + ma;
                sc0[nt][3] = sc0[nt][3] * 0.125f + mb;
                tmax0 = fmaxf(tmax0, fmaxf(sc0[nt][0], sc0[nt][1]));
                tmax1 = fmaxf(tmax1, fmaxf(sc0[nt][2], sc0[nt][3]));
            }
            tmax0 = fmaxf(tmax0, __shfl_xor_sync(0xffffffffu, tmax0, 1));
            tmax0 = fmaxf(tmax0, __shfl_xor_sync(0xffffffffu, tmax0, 2));
            tmax1 = fmaxf(tmax1, __shfl_xor_sync(0xffffffffu, tmax1, 1));
            tmax1 = fmaxf(tmax1, __shfl_xor_sync(0xffffffffu, tmax1, 2));

            const float mn0 = fmaxf(mA0, tmax0);
            const float mn1 = fmaxf(mA1, tmax1);
            const float cr0 = __expf(mA0 - mn0);
            const float cr1 = __expf(mA1 - mn1);
            mA0 = mn0; mA1 = mn1;

            float ls0 = 0.f, ls1 = 0.f;
            float* prow0 = Ps + (wid * 32 + r) * PS_STR + 2 * cq;
            float* prow8 = prow0 + 8 * PS_STR;
            #pragma unroll
            for (int nt = 0; nt < 8; nt++) {
                const float p0 = __expf(sc0[nt][0] - mn0);
                const float p1 = __expf(sc0[nt][1] - mn0);
                const float p2 = __expf(sc0[nt][2] - mn1);
                const float p3 = __expf(sc0[nt][3] - mn1);
                ls0 += p0 + p1;
                ls1 += p2 + p3;
                float2 w0, w1;
                w0.x = to_tf32(p0); w0.y = to_tf32(p1);
                w1.x = to_tf32(p2); w1.y = to_tf32(p3);
                *(float2*)(prow0 + nt * 8) = w0;
                *(float2*)(prow8 + nt * 8) = w1;
                o0[nt][0] *= cr0; o0[nt][1] *= cr0;
                o0[nt][2] *= cr1; o0[nt][3] *= cr1;
            }
            ls0 += __shfl_xor_sync(0xffffffffu, ls0, 1);
            ls0 += __shfl_xor_sync(0xffffffffu, ls0, 2);
            ls1 += __shfl_xor_sync(0xffffffffu, ls1, 1);
            ls1 += __shfl_xor_sync(0xffffffffu, ls1, 2);
            lA0 = lA0 * cr0 + ls0;
            lA1 = lA1 * cr1 + ls1;
        }

        // ---- online softmax, m-tile 1 ----
        {
            float tmax0 = -1e30f, tmax1 = -1e30f;
            #pragma unroll
            for (int nt = 0; nt < 8; nt++) {
                const int j = nt * 8 + 2 * cq;
                const float ma = madd[j], mb = madd[j + 1];
                sc1[nt][0] = sc1[nt][0] * 0.125f + ma;
                sc1[nt][1] = sc1[nt][1] * 0.125f + mb;
                sc1[nt][2] = sc1[nt][2] * 0.125f + ma;
                sc1[nt][3] = sc1[nt][3] * 0.125f + mb;
                tmax0 = fmaxf(tmax0, fmaxf(sc1[nt][0], sc1[nt][1]));
                tmax1 = fmaxf(tmax1, fmaxf(sc1[nt][2], sc1[nt][3]));
            }
            tmax0 = fmaxf(tmax0, __shfl_xor_sync(0xffffffffu, tmax0, 1));
            tmax0 = fmaxf(tmax0, __shfl_xor_sync(0xffffffffu, tmax0, 2));
            tmax1 = fmaxf(tmax1, __shfl_xor_sync(0xffffffffu, tmax1, 1));
            tmax1 = fmaxf(tmax1, __shfl_xor_sync(0xffffffffu, tmax1, 2));

            const float mn0 = fmaxf(mB0, tmax0);
            const float mn1 = fmaxf(mB1, tmax1);
            const float cr0 = __expf(mB0 - mn0);
            const float cr1 = __expf(mB1 - mn1);
            mB0 = mn0; mB1 = mn1;

            float ls0 = 0.f, ls1 = 0.f;
            float* prow0 = Ps + (wid * 32 + 16 + r) * PS_STR + 2 * cq;
            float* prow8 = prow0 + 8 * PS_STR;
            #pragma unroll
            for (int nt = 0; nt < 8; nt++) {
                const float p0 = __expf(sc1[nt][0] - mn0);
                const float p1 = __expf(sc1[nt][1] - mn0);
                const float p2 = __expf(sc1[nt][2] - mn1);
                const float p3 = __expf(sc1[nt][3] - mn1);
                ls0 += p0 + p1;
                ls1 += p2 + p3;
                float2 w0, w1;
                w0.x = to_tf32(p0); w0.y = to_tf32(p1);
                w1.x = to_tf32(p2); w1.y = to_tf32(p3);
                *(float2*)(prow0 + nt * 8) = w0;
                *(float2*)(prow8 + nt * 8) = w1;
                o1[nt][0] *= cr0; o1[nt][1] *= cr0;
                o1[nt][2] *= cr1; o1[nt][3] *= cr1;
            }
            ls0 += __shfl_xor_sync(0xffffffffu, ls0, 1);
            ls0 += __shfl_xor_sync(0xffffffffu, ls0, 2);
            ls1 += __shfl_xor_sync(0xffffffffu, ls1, 1);
            ls1 += __shfl_xor_sync(0xffffffffu, ls1, 2);
            lB0 = lB0 * cr0 + ls0;
            lB1 = lB1 * cr1 + ls1;
        }

        __syncwarp();   // Ps rows are warp-private; order STS->LDS

        // ---- O += P @ V; each V fragment feeds 2 MMAs ----
        #pragma unroll
        for (int ks = 0; ks < 8; ks++) {
            const int kb = ks * 8;
            uint32_t a0[4], a1[4];
            const float* pa0 = Ps + (wid * 32 + r) * PS_STR + kb;
            a0[0] = __float_as_uint(pa0[cq]);
            a0[1] = __float_as_uint(pa0[8 * PS_STR + cq]);
            a0[2] = __float_as_uint(pa0[cq + 4]);
            a0[3] = __float_as_uint(pa0[8 * PS_STR + cq + 4]);
            const float* pa1 = pa0 + 16 * PS_STR;
            a1[0] = __float_as_uint(pa1[cq]);
            a1[1] = __float_as_uint(pa1[8 * PS_STR + cq]);
            a1[2] = __float_as_uint(pa1[cq + 4]);
            a1[3] = __float_as_uint(pa1[8 * PS_STR + cq + 4]);
            #pragma unroll
            for (int nt = 0; nt < 8; nt++) {
                uint32_t b[2];
                const float* pv = Vst + (kb + cq) * VS_STR + nt * 8 + r;
                b[0] = __float_as_uint(pv[0]);
                b[1] = __float_as_uint(pv[4 * VS_STR]);
                mma_tf32_16x8x8(o0[nt], a0, b);
                mma_tf32_16x8x8(o1[nt], a1, b);
            }
        }

        asm volatile("cp.async.wait_all;" ::: "memory");
        __syncthreads();   // stage swap + P reuse
    }

    // ---- epilogue: write tf32-rounded ctx (consumed by FC gemm) ----
    const int h = nh % HH;
    {
        const float inv0 = 1.f / lA0;
        const float inv1 = 1.f / lA1;
        const int q = q0 + wid * 32 + r;
        float* outp  = (stream ? ctx1 : ctx0)
                     + ((size_t)(n * SDIM + q)) * DDIM + h * DKH;
        float* outp8 = outp + 8 * DDIM;
        #pragma unroll
        for (int nt = 0; nt < 8; nt++) {
            const int dk = nt * 8 + 2 * cq;
            float2 v0, v1;
            v0.x = to_tf32(o0[nt][0] * inv0); v0.y = to_tf32(o0[nt][1] * inv0);
            v1.x = to_tf32(o0[nt][2] * inv1); v1.y = to_tf32(o0[nt][3] * inv1);
            *(float2*)(outp  + dk) = v0;
            *(float2*)(outp8 + dk) = v1;
        }
    }
    {
        const float inv0 = 1.f / lB0;
        const float inv1 = 1.f / lB1;
        const int q = q0 + wid * 32 + 16 + r;
        float* outp  = (stream ? ctx1 : ctx0)
                     + ((size_t)(n * SDIM + q)) * DDIM + h * DKH;
        float* outp8 = outp + 8 * DDIM;
        #pragma unroll
        for (int nt = 0; nt < 8; nt++) {
            const int dk = nt * 8 + 2 * cq;
            float2 v0, v1;
            v0.x = to_tf32(o1[nt][0] * inv0); v0.y = to_tf32(o1[nt][1] * inv0);
            v1.x = to_tf32(o1[nt][2] * inv1); v1.y = to_tf32(o1[nt][3] * inv1);
            *(float2*)(outp  + dk) = v0;
            *(float2*)(outp8 + dk) = v1;
        }
    }
}

// ---------------------------------------------------------------------------
extern "C" void kernel_launch(void* const* d_in, const int* in_sizes, int n_in,
                              void* d_out, int out_size)
{
    const float* Qpoi = (const float*)d_in[0];
    const float* Qsvi = (const float*)d_in[1];
    const float* Kin  = (const float*)d_in[2];
    const float* Vin  = (const float*)d_in[3];
    const unsigned char* mask = (const unsigned char*)d_in[4];
    const float* wq_poi_w = (const float*)d_in[5];
    const float* wq_poi_b = (const float*)d_in[6];
    const float* wq_svi_w = (const float*)d_in[7];
    const float* wq_svi_b = (const float*)d_in[8];
    const float* wk_w = (const float*)d_in[9];
    const float* wk_b = (const float*)d_in[10];
    const float* wv_w = (const float*)d_in[11];
    const float* wv_b = (const float*)d_in[12];
    const float* fc_w = (const float*)d_in[13];
    const float* fc_b = (const float*)d_in[14];
    float* out = (float*)d_out;

    float *Qp, *Qs, *Kh, *Vh, *c0, *c1, *madd, *wt;
    cudaGetSymbolAddress((void**)&Qp, g_Qp);
    cudaGetSymbolAddress((void**)&Qs, g_Qs);
    cudaGetSymbolAddress((void**)&Kh, g_Kh);
    cudaGetSymbolAddress((void**)&Vh, g_Vh);
    cudaGetSymbolAddress((void**)&c0, g_ctx0);
    cudaGetSymbolAddress((void**)&c1, g_ctx1);
    cudaGetSymbolAddress((void**)&madd, g_madd);
    cudaGetSymbolAddress((void**)&wt, g_wt);

    float* wt_q_poi = wt + 0 * (size_t)DDIM * DDIM;
    float* wt_q_svi = wt + 1 * (size_t)DDIM * DDIM;
    float* wt_k     = wt + 2 * (size_t)DDIM * DDIM;
    float* wt_v     = wt + 3 * (size_t)DDIM * DDIM;
    float* wt_fc    = wt + 4 * (size_t)DDIM * DDIM;

    // 0a) canonicalize padding mask
    mask_expand_kernel<<<1, 1024>>>(mask, madd);

    // 0b) pre-round the 5 weight matrices to tf32
    W5 w5;
    w5.src[0] = (const float4*)wq_poi_w; w5.dst[0] = (float4*)wt_q_poi;
    w5.src[1] = (const float4*)wq_svi_w; w5.dst[1] = (float4*)wt_q_svi;
    w5.src[2] = (const float4*)wk_w;     w5.dst[2] = (float4*)wt_k;
    w5.src[3] = (const float4*)wv_w;     w5.dst[3] = (float4*)wt_v;
    w5.src[4] = (const float4*)fc_w;     w5.dst[4] = (float4*)wt_fc;
    wcvt_kernel<<<dim3(DDIM * DDIM / 4 / 256, 1, 5), 256>>>(w5);

    // 1) projections -> [N,H,S,DK] (one batched launch, z = 4)
    Batch4 proj;
    proj.A[0] = Qpoi; proj.W[0] = wt_q_poi; proj.bias[0] = wq_poi_b; proj.out[0] = Qp;
    proj.A[1] = Qsvi; proj.W[1] = wt_q_svi; proj.bias[1] = wq_svi_b; proj.out[1] = Qs;
    proj.A[2] = Kin;  proj.W[2] = wt_k;     proj.bias[2] = wk_b;     proj.out[2] = Kh;
    proj.A[3] = Vin;  proj.W[3] = wt_v;     proj.bias[3] = wv_b;     proj.out[3] = Vh;
    gemm_tc<0><<<dim3(DDIM / 128, (SDIM * NB) / 128, 4), 256>>>(proj);

    // 2) attention (tensor cores, tf32; both streams in z)
    const int smem = (2 * KSZ + 2 * VSZ + AQT * PS_STR + 2 * AKT) * (int)sizeof(float);
    cudaFuncSetAttribute((const void*)attn_tc,
                         cudaFuncAttributeMaxDynamicSharedMemorySize, smem);
    attn_tc<<<dim3(SDIM / AQT, NB * HH, 2), 128, smem>>>(Qp, Qs, Kh, Vh, madd, c0, c1);

    // 3) output FC -> [S,N,D] (one batched launch, z = 2)
    Batch4 fc;
    fc.A[0] = c0; fc.W[0] = wt_fc; fc.bias[0] = fc_b; fc.out[0] = out;
    fc.A[1] = c1; fc.W[1] = wt_fc; fc.bias[1] = fc_b; fc.out[1] = out + (size_t)SDIM * NB * DDIM;
    fc.A[2] = c0; fc.W[2] = wt_fc; fc.bias[2] = fc_b; fc.out[2] = out;  // unused
    fc.A[3] = c1; fc.W[3] = wt_fc; fc.bias[3] = fc_b; fc.out[3] = out + (size_t)SDIM * NB * DDIM;  // unused
    gemm_tc<1><<<dim3(DDIM / 128, (SDIM * NB) / 128, 2), 256>>>(fc);
}

// round 10
// speedup vs baseline: 1.6818x; 1.0002x over previous
#include <cuda_runtime.h>
#include <cstdint>

// Problem dims
#define SDIM 1024
#define NB   8
#define DDIM 1024
#define HH   16
#define DKH  64

// ---------------- scratch (device globals; no allocations allowed) ----------
__device__ float g_Qp[(size_t)NB * HH * SDIM * DKH];   // [N,H,S,DK] (tf32-rounded)
__device__ float g_Qs[(size_t)NB * HH * SDIM * DKH];
__device__ float g_Kh[(size_t)NB * HH * SDIM * DKH];
__device__ float g_Vh[(size_t)NB * HH * SDIM * DKH];
__device__ float g_ctx0[(size_t)NB * SDIM * DDIM];     // [N,S,D] (tf32-rounded)
__device__ float g_ctx1[(size_t)NB * SDIM * DDIM];
__device__ float g_madd[(size_t)NB * SDIM];            // 0 or -1e9 additive mask
__device__ float g_wt[5][(size_t)DDIM * DDIM];         // tf32-rounded weights

// ---------------- mask canonicalization -------------------------------------
__global__ void mask_expand_kernel(const unsigned char* __restrict__ m,
                                   float* __restrict__ madd)
{
    __shared__ int s_big, s_nonmult4, s_anynz;
    const int t = threadIdx.x;               // 1024 threads, single block
    if (t == 0) { s_big = 0; s_nonmult4 = 0; s_anynz = 0; }
    __syncthreads();

    const int total = NB * SDIM;             // 8192 entries
    int big = 0, nonm4 = 0, anynz = 0;
    for (int i = t; i < total; i += 1024) {
        unsigned char b = m[i];
        if (b > 1) big = 1;
        if (b) { anynz = 1; if (i & 3) nonm4 = 1; }
    }
    if (big)   atomicOr(&s_big, 1);
    if (nonm4) atomicOr(&s_nonmult4, 1);
    if (anynz) atomicOr(&s_anynz, 1);
    __syncthreads();

    const bool width4 = s_big || !s_nonmult4 || !s_anynz;

    for (int i = t; i < total; i += 1024) {
        unsigned char v;
        if (width4) {
            v = (unsigned char)(m[4 * i] | m[4 * i + 1] | m[4 * i + 2] | m[4 * i + 3]);
        } else {
            v = m[i];
        }
        madd[i] = v ? -1e9f : 0.f;
    }
}

// ---------------- tf32 helpers ----------------------------------------------
__device__ __forceinline__ float to_tf32(float x) {
    float r;
    asm("cvt.rna.tf32.f32 %0, %1;" : "=f"(r) : "f"(x));
    return r;
}

__device__ __forceinline__ void mma_tf32_16x8x8(float* c, const uint32_t* a,
                                                const uint32_t* b)
{
    asm volatile(
        "mma.sync.aligned.m16n8k8.row.col.f32.tf32.tf32.f32 "
        "{%0,%1,%2,%3}, {%4,%5,%6,%7}, {%8,%9}, {%0,%1,%2,%3};"
        : "+f"(c[0]), "+f"(c[1]), "+f"(c[2]), "+f"(c[3])
        : "r"(a[0]), "r"(a[1]), "r"(a[2]), "r"(a[3]), "r"(b[0]), "r"(b[1]));
}

__device__ __forceinline__ void cp16(void* smem, const void* gmem) {
    uint32_t s = (uint32_t)__cvta_generic_to_shared(smem);
    asm volatile("cp.async.ca.shared.global [%0], [%1], 16;" :: "r"(s), "l"(gmem));
}

// ---------------- weight pre-rounding ----------------------------------------
struct W5 { const float4* src[5]; float4* dst[5]; };
__global__ void wcvt_kernel(W5 w)
{
    const int z = blockIdx.z;
    const float4* __restrict__ s = w.src[z];
    float4* __restrict__ d = w.dst[z];
    const int i = blockIdx.x * blockDim.x + threadIdx.x;   // 262144 float4
    float4 v = s[i];
    v.x = to_tf32(v.x); v.y = to_tf32(v.y);
    v.z = to_tf32(v.z); v.w = to_tf32(v.w);
    d[i] = v;
}

// k-permuted smem slab layout (16 k per row, 16 floats per row):
//   logical pos  p = (k%4)*4 + k/4; physical = p ^ (((row>>1)&3)<<2).
template <bool CVT>
__device__ __forceinline__ void store_slab(float* stage, int row, int c4i, float4 v)
{
    const int swz = ((row >> 1) & 3) << 2;
    float* p = stage + row * 16;
    if (CVT) {
        p[(c4i      ) ^ swz] = to_tf32(v.x);
        p[(c4i +  4) ^ swz] = to_tf32(v.y);
        p[(c4i +  8) ^ swz] = to_tf32(v.z);
        p[(c4i + 12) ^ swz] = to_tf32(v.w);
    } else {
        p[(c4i      ) ^ swz] = v.x;
        p[(c4i +  4) ^ swz] = v.y;
        p[(c4i +  8) ^ swz] = v.z;
        p[(c4i + 12) ^ swz] = v.w;
    }
}

// ---------------- batched, pipelined tensor-core GEMM -----------------------
struct Batch4 {
    const float* A[4];
    const float* W[4];
    const float* bias[4];
    float* out[4];
};

template <int MODE>
__global__ void __launch_bounds__(256, 2)
gemm_tc(Batch4 batch)
{
    constexpr int BM = 128, BN = 128, BK = 16, KD = 1024;
    __shared__ float As[2][BM * 16];
    __shared__ float Bs[2][BN * 16];

    const int z = blockIdx.z;
    const float* __restrict__ A    = batch.A[z];
    const float* __restrict__ W    = batch.W[z];
    const float* __restrict__ bias = batch.bias[z];
    float* __restrict__ out        = batch.out[z];

    const int tid  = threadIdx.x;
    const int wid  = tid >> 5;
    const int lane = tid & 31;
    const int wm = wid & 1;
    const int wn = wid >> 1;
    const int m0 = blockIdx.y * BM;
    const int n0 = blockIdx.x * BN;

    const int r  = lane >> 2;
    const int cq = lane & 3;
    const int cqo = cq * 4;

    const int lrow0 = tid >> 2;               // 0..63
    const int lrow1 = lrow0 + 64;             // 64..127
    const int c4i   = tid & 3;
    const int lc4   = c4i << 2;

    const float* Aptr = A + (size_t)m0 * KD;
    const float* Wptr = W + (size_t)n0 * KD;

    float acc[4][4][4];
    #pragma unroll
    for (int mt = 0; mt < 4; mt++)
        #pragma unroll
        for (int nt = 0; nt < 4; nt++)
            #pragma unroll
            for (int i = 0; i < 4; i++) acc[mt][nt][i] = 0.f;

    float4 pa0, pa1, pb0, pb1;

    pa0 = *(const float4*)(Aptr + (size_t)lrow0 * KD + lc4);
    pa1 = *(const float4*)(Aptr + (size_t)lrow1 * KD + lc4);
    pb0 = *(const float4*)(Wptr + (size_t)lrow0 * KD + lc4);
    pb1 = *(const float4*)(Wptr + (size_t)lrow1 * KD + lc4);
    store_slab<MODE == 0>(As[0], lrow0, c4i, pa0);
    store_slab<MODE == 0>(As[0], lrow1, c4i, pa1);
    store_slab<false>(Bs[0], lrow0, c4i, pb0);
    store_slab<false>(Bs[0], lrow1, c4i, pb1);
    __syncthreads();

    for (int it = 0; it < KD / BK; it++) {
        const int cur = it & 1;
        const int nxt = cur ^ 1;
        const bool more = (it + 1) < KD / BK;

        if (more) {
            const int kn = (it + 1) * BK;
            pa0 = *(const float4*)(Aptr + (size_t)lrow0 * KD + kn + lc4);
            pa1 = *(const float4*)(Aptr + (size_t)lrow1 * KD + kn + lc4);
            pb0 = *(const float4*)(Wptr + (size_t)lrow0 * KD + kn + lc4);
            pb1 = *(const float4*)(Wptr + (size_t)lrow1 * KD + kn + lc4);
        }

        const float* Asc = As[cur];
        const float* Bsc = Bs[cur];

        uint32_t bf0[4][2], bf1[4][2];
        #pragma unroll
        for (int nt = 0; nt < 4; nt++) {
            const int nrow = wn * 32 + nt * 8 + r;
            const int swz = ((nrow >> 1) & 3) << 2;
            const float4 bl = *(const float4*)(Bsc + nrow * 16 + (cqo ^ swz));
            bf0[nt][0] = __float_as_uint(bl.x);
            bf0[nt][1] = __float_as_uint(bl.y);
            bf1[nt][0] = __float_as_uint(bl.z);
            bf1[nt][1] = __float_as_uint(bl.w);
        }

        #pragma unroll
        for (int mt = 0; mt < 4; mt++) {
            const int mr = wm * 64 + mt * 16 + r;
            const int swz = ((mr >> 1) & 3) << 2;
            const float4 lf0 = *(const float4*)(Asc + mr * 16 + (cqo ^ swz));
            const float4 lf8 = *(const float4*)(Asc + (mr + 8) * 16 + (cqo ^ swz));

            uint32_t a0[4], a1[4];
            a0[0] = __float_as_uint(lf0.x); a0[1] = __float_as_uint(lf8.x);
            a0[2] = __float_as_uint(lf0.y); a0[3] = __float_as_uint(lf8.y);
            a1[0] = __float_as_uint(lf0.z); a1[1] = __float_as_uint(lf8.z);
            a1[2] = __float_as_uint(lf0.w); a1[3] = __float_as_uint(lf8.w);

            #pragma unroll
            for (int nt = 0; nt < 4; nt++)
                mma_tf32_16x8x8(acc[mt][nt], a0, bf0[nt]);
            #pragma unroll
            for (int nt = 0; nt < 4; nt++)
                mma_tf32_16x8x8(acc[mt][nt], a1, bf1[nt]);
        }

        if (more) {
            store_slab<MODE == 0>(As[nxt], lrow0, c4i, pa0);
            store_slab<MODE == 0>(As[nxt], lrow1, c4i, pa1);
            store_slab<false>(Bs[nxt], lrow0, c4i, pb0);
            store_slab<false>(Bs[nxt], lrow1, c4i, pb1);
        }
        __syncthreads();
    }

    const int cpair = (lane & 3) * 2;
    #pragma unroll
    for (int nt = 0; nt < 4; nt++) {
        const int dout = n0 + wn * 32 + nt * 8 + cpair;
        const float2 bb = *(const float2*)(bias + dout);
        #pragma unroll
        for (int mt = 0; mt < 4; mt++) {
            #pragma unroll
            for (int half = 0; half < 2; half++) {
                const int m = m0 + wm * 64 + mt * 16 + r + half * 8;
                float2 v;
                v.x = acc[mt][nt][half * 2 + 0] + bb.x;
                v.y = acc[mt][nt][half * 2 + 1] + bb.y;
                if (MODE == 0) {
                    v.x = to_tf32(v.x);
                    v.y = to_tf32(v.y);
                    const int s = m >> 3, n = m & 7;
                    const int h = dout >> 6, dk = dout & 63;
                    *(float2*)(out + ((size_t)((n * HH + h) * SDIM + s)) * DKH + dk) = v;
                } else {
                    const int n = m >> 10, s = m & 1023;
                    *(float2*)(out + ((size_t)(s * NB + n)) * DDIM + dout) = v;
                }
            }
        }
    }
}

// ---------------- tensor-core flash attention --------------------------------
// 128 threads, 4 warps; warp w owns 32 q rows (two m16 tiles). K/V fragment
// loads shared across both m-tiles -> half the smem fragment traffic.
// Double-buffered cp.async K/V prefetch.
#define AQT 128
#define AKT 64
#define KS_STR 68
#define VS_STR 72
#define PS_STR 68
#define KSZ (AKT * KS_STR)
#define VSZ (AKT * VS_STR)

__global__ void __launch_bounds__(128, 2)
attn_tc(const float* __restrict__ Qp, const float* __restrict__ Qsv,
        const float* __restrict__ Kh, const float* __restrict__ Vh,
        const float* __restrict__ maddg,
        float* __restrict__ ctx0, float* __restrict__ ctx1)
{
    extern __shared__ float sm[];
    float* KsB   = sm;                        // [2][64][KS_STR]
    float* VsB   = KsB + 2 * KSZ;             // [2][64][VS_STR]
    float* Ps    = VsB + 2 * VSZ;             // [128][PS_STR]
    float* maddB = Ps + AQT * PS_STR;         // [2][64]

    const int nh = blockIdx.y;
    const int n  = nh / HH;
    const int stream = blockIdx.z;
    const int q0 = blockIdx.x * AQT;
    const int tid = threadIdx.x;
    const int wid = tid >> 5;                 // 0..3
    const int lane = tid & 31;
    const int r  = lane >> 2;
    const int cq = lane & 3;

    const float* Qb = (stream ? Qsv : Qp) + (size_t)nh * SDIM * DKH;
    const float* Kb = Kh + (size_t)nh * SDIM * DKH;
    const float* Vb = Vh + (size_t)nh * SDIM * DKH;
    const float* mrow = maddg + n * SDIM;

    // Q fragments for the warp's two m16 tiles (pre-rounded -> raw loads)
    uint32_t qf0[8][4], qf1[8][4];
    {
        const float* qa = Qb + (size_t)(q0 + wid * 32 + r) * DKH;
        const float* qb = qa + 8 * DKH;
        const float* qc = qa + 16 * DKH;
        const float* qd = qa + 24 * DKH;
        #pragma unroll
        for (int ks = 0; ks < 8; ks++) {
            qf0[ks][0] = __float_as_uint(qa[ks * 8 + cq]);
            qf0[ks][1] = __float_as_uint(qb[ks * 8 + cq]);
            qf0[ks][2] = __float_as_uint(qa[ks * 8 + cq + 4]);
            qf0[ks][3] = __float_as_uint(qb[ks * 8 + cq + 4]);
            qf1[ks][0] = __float_as_uint(qc[ks * 8 + cq]);
            qf1[ks][1] = __float_as_uint(qd[ks * 8 + cq]);
            qf1[ks][2] = __float_as_uint(qc[ks * 8 + cq + 4]);
            qf1[ks][3] = __float_as_uint(qd[ks * 8 + cq + 4]);
        }
    }

    float o0[8][4], o1[8][4];
    #pragma unroll
    for (int nt = 0; nt < 8; nt++)
        #pragma unroll
        for (int i = 0; i < 4; i++) { o0[nt][i] = 0.f; o1[nt][i] = 0.f; }
    float mA0 = -1e30f, mA1 = -1e30f, lA0 = 0.f, lA1 = 0.f;   // m-tile 0, rows r / r+8
    float mB0 = -1e30f, mB1 = -1e30f, lB0 = 0.f, lB1 = 0.f;   // m-tile 1

    // prologue fill: stage 0, k0 = 0
    {
        const float* ksrc = Kb;
        const float* vsrc = Vb;
        #pragma unroll
        for (int i = 0; i < 8; i++) {
            const int idx = tid + 128 * i;         // 0..1023
            const int row = idx >> 4;
            const int c4  = (idx & 15) << 2;
            cp16(KsB + row * KS_STR + c4, ksrc + idx * 4);
            cp16(VsB + row * VS_STR + c4, vsrc + idx * 4);
        }
        if (tid < AKT) maddB[tid] = mrow[tid];
        asm volatile("cp.async.wait_all;" ::: "memory");
    }
    __syncthreads();

    for (int kt = 0; kt < SDIM / AKT; kt++) {
        const int cur = kt & 1;
        const bool more = (kt + 1) < SDIM / AKT;

        // prefetch next K/V tile into the other stage (waited at loop end)
        if (more) {
            const int kn = (kt + 1) * AKT;
            const float* ksrc = Kb + (size_t)kn * DKH;
            const float* vsrc = Vb + (size_t)kn * DKH;
            float* kd = KsB + (cur ^ 1) * KSZ;
            float* vd = VsB + (cur ^ 1) * VSZ;
            #pragma unroll
            for (int i = 0; i < 8; i++) {
                const int idx = tid + 128 * i;
                const int row = idx >> 4;
                const int c4  = (idx & 15) << 2;
                cp16(kd + row * KS_STR + c4, ksrc + idx * 4);
                cp16(vd + row * VS_STR + c4, vsrc + idx * 4);
            }
            if (tid < AKT) maddB[(cur ^ 1) * AKT + tid] = mrow[kn + tid];
        }

        const float* Kst = KsB + cur * KSZ;
        const float* Vst = VsB + cur * VSZ;
        const float* madd = maddB + cur * AKT;

        // ---- scores for both m-tiles; each K fragment feeds 2 MMAs ----
        float sc0[8][4], sc1[8][4];
        #pragma unroll
        for (int nt = 0; nt < 8; nt++)
            #pragma unroll
            for (int i = 0; i < 4; i++) { sc0[nt][i] = 0.f; sc1[nt][i] = 0.f; }

        #pragma unroll
        for (int ks = 0; ks < 8; ks++) {
            const int kb = ks * 8;
            #pragma unroll
            for (int nt = 0; nt < 8; nt++) {
                uint32_t b[2];
                const float* p = Kst + (nt * 8 + r) * KS_STR + kb + cq;
                b[0] = __float_as_uint(p[0]);
                b[1] = __float_as_uint(p[4]);
                mma_tf32_16x8x8(sc0[nt], qf0[ks], b);
                mma_tf32_16x8x8(sc1[nt], qf1[ks], b);
            }
        }

        // ---- online softmax, m-tile 0 ----
        {
            float tmax0 = -1e30f, tmax1 = -1e30f;
            #pragma unroll
            for (int nt = 0; nt < 8; nt++) {
                const int j = nt * 8 + 2 * cq;
                const float ma = madd[j], mb = madd[j + 1];
                sc0[nt][0] = sc0[nt][0] * 0.125f + ma;
                sc0[nt][1] = sc0[nt][1] * 0.125f + mb;
                sc0[nt][2] = sc0[nt][2] * 0.125f + ma;
                sc0[nt][3] = sc0[nt][3] * 0.125f + mb;
                tmax0 = fmaxf(tmax0, fmaxf(sc0[nt][0], sc0[nt][1]));
                tmax1 = fmaxf(tmax1, fmaxf(sc0[nt][2], sc0[nt][3]));
            }
            tmax0 = fmaxf(tmax0, __shfl_xor_sync(0xffffffffu, tmax0, 1));
            tmax0 = fmaxf(tmax0, __shfl_xor_sync(0xffffffffu, tmax0, 2));
            tmax1 = fmaxf(tmax1, __shfl_xor_sync(0xffffffffu, tmax1, 1));
            tmax1 = fmaxf(tmax1, __shfl_xor_sync(0xffffffffu, tmax1, 2));

            const float mn0 = fmaxf(mA0, tmax0);
            const float mn1 = fmaxf(mA1, tmax1);
            const float cr0 = __expf(mA0 - mn0);
            const float cr1 = __expf(mA1 - mn1);
            mA0 = mn0; mA1 = mn1;

            float ls0 = 0.f, ls1 = 0.f;
            float* prow0 = Ps + (wid * 32 + r) * PS_STR + 2 * cq;
            float* prow8 = prow0 + 8 * PS_STR;
            #pragma unroll
            for (int nt = 0; nt < 8; nt++) {
                const float p0 = __expf(sc0[nt][0] - mn0);
                const float p1 = __expf(sc0[nt][1] - mn0);
                const float p2 = __expf(sc0[nt][2] - mn1);
                const float p3 = __expf(sc0[nt][3] - mn1);
                ls0 += p0 + p1;
                ls1 += p2 + p3;
                float2 w0, w1;
                w0.x = to_tf32(p0); w0.y = to_tf32(p1);
                w1.x = to_tf32(p2); w1.y = to_tf32(p3);
                *(float2*)(prow0 + nt * 8) = w0;
                *(float2*)(prow8 + nt * 8) = w1;
                o0[nt][0] *= cr0; o0[nt][1] *= cr0;
                o0[nt][2] *= cr1; o0[nt][3] *= cr1;
            }
            ls0 += __shfl_xor_sync(0xffffffffu, ls0, 1);
            ls0 += __shfl_xor_sync(0xffffffffu, ls0, 2);
            ls1 += __shfl_xor_sync(0xffffffffu, ls1, 1);
            ls1 += __shfl_xor_sync(0xffffffffu, ls1, 2);
            lA0 = lA0 * cr0 + ls0;
            lA1 = lA1 * cr1 + ls1;
        }

        // ---- online softmax, m-tile 1 ----
        {
            float tmax0 = -1e30f, tmax1 = -1e30f;
            #pragma unroll
            for (int nt = 0; nt < 8; nt++) {
                const int j = nt * 8 + 2 * cq;
                const float ma = madd[j], mb = madd[j + 1];
                sc1[nt][0] = sc1[nt][0] * 0.125f + ma;
                sc1[nt][1] = sc1[nt][1] * 0.125f + mb;
                sc1[nt][2] = sc1[nt][2] * 0.125f + ma;
                sc1[nt][3] = sc1[nt][3] * 0.125f + mb;
                tmax0 = fmaxf(tmax0, fmaxf(sc1[nt][0], sc1[nt][1]));
                tmax1 = fmaxf(tmax1, fmaxf(sc1[nt][2], sc1[nt][3]));
            }
            tmax0 = fmaxf(tmax0, __shfl_xor_sync(0xffffffffu, tmax0, 1));
            tmax0 = fmaxf(tmax0, __shfl_xor_sync(0xffffffffu, tmax0, 2));
            tmax1 = fmaxf(tmax1, __shfl_xor_sync(0xffffffffu, tmax1, 1));
            tmax1 = fmaxf(tmax1, __shfl_xor_sync(0xffffffffu, tmax1, 2));

            const float mn0 = fmaxf(mB0, tmax0);
            const float mn1 = fmaxf(mB1, tmax1);
            const float cr0 = __expf(mB0 - mn0);
            const float cr1 = __expf(mB1 - mn1);
            mB0 = mn0; mB1 = mn1;

            float ls0 = 0.f, ls1 = 0.f;
            float* prow0 = Ps + (wid * 32 + 16 + r) * PS_STR + 2 * cq;
            float* prow8 = prow0 + 8 * PS_STR;
            #pragma unroll
            for (int nt = 0; nt < 8; nt++) {
                const float p0 = __expf(sc1[nt][0] - mn0);
                const float p1 = __expf(sc1[nt][1] - mn0);
                const float p2 = __expf(sc1[nt][2] - mn1);
                const float p3 = __expf(sc1[nt][3] - mn1);
                ls0 += p0 + p1;
                ls1 += p2 + p3;
                float2 w0, w1;
                w0.x = to_tf32(p0); w0.y = to_tf32(p1);
                w1.x = to_tf32(p2); w1.y = to_tf32(p3);
                *(float2*)(prow0 + nt * 8) = w0;
                *(float2*)(prow8 + nt * 8) = w1;
                o1[nt][0] *= cr0; o1[nt][1] *= cr0;
                o1[nt][2] *= cr1; o1[nt][3] *= cr1;
            }
            ls0 += __shfl_xor_sync(0xffffffffu, ls0, 1);
            ls0 += __shfl_xor_sync(0xffffffffu, ls0, 2);
            ls1 += __shfl_xor_sync(0xffffffffu, ls1, 1);
            ls1 += __shfl_xor_sync(0xffffffffu, ls1, 2);
            lB0 = lB0 * cr0 + ls0;
            lB1 = lB1 * cr1 + ls1;
        }

        __syncwarp();   // Ps rows are warp-private; order STS->LDS

        // ---- O += P @ V; each V fragment feeds 2 MMAs ----
        #pragma unroll
        for (int ks = 0; ks < 8; ks++) {
            const int kb = ks * 8;
            uint32_t a0[4], a1[4];
            const float* pa0 = Ps + (wid * 32 + r) * PS_STR + kb;
            a0[0] = __float_as_uint(pa0[cq]);
            a0[1] = __float_as_uint(pa0[8 * PS_STR + cq]);
            a0[2] = __float_as_uint(pa0[cq + 4]);
            a0[3] = __float_as_uint(pa0[8 * PS_STR + cq + 4]);
            const float* pa1 = pa0 + 16 * PS_STR;
            a1[0] = __float_as_uint(pa1[cq]);
            a1[1] = __float_as_uint(pa1[8 * PS_STR + cq]);
            a1[2] = __float_as_uint(pa1[cq + 4]);
            a1[3] = __float_as_uint(pa1[8 * PS_STR + cq + 4]);
            #pragma unroll
            for (int nt = 0; nt < 8; nt++) {
                uint32_t b[2];
                const float* pv = Vst + (kb + cq) * VS_STR + nt * 8 + r;
                b[0] = __float_as_uint(pv[0]);
                b[1] = __float_as_uint(pv[4 * VS_STR]);
                mma_tf32_16x8x8(o0[nt], a0, b);
                mma_tf32_16x8x8(o1[nt], a1, b);
            }
        }

        asm volatile("cp.async.wait_all;" ::: "memory");
        __syncthreads();   // stage swap + P reuse
    }

    // ---- epilogue: write tf32-rounded ctx (consumed by FC gemm) ----
    const int h = nh % HH;
    {
        const float inv0 = 1.f / lA0;
        const float inv1 = 1.f / lA1;
        const int q = q0 + wid * 32 + r;
        float* outp  = (stream ? ctx1 : ctx0)
                     + ((size_t)(n * SDIM + q)) * DDIM + h * DKH;
        float* outp8 = outp + 8 * DDIM;
        #pragma unroll
        for (int nt = 0; nt < 8; nt++) {
            const int dk = nt * 8 + 2 * cq;
            float2 v0, v1;
            v0.x = to_tf32(o0[nt][0] * inv0); v0.y = to_tf32(o0[nt][1] * inv0);
            v1.x = to_tf32(o0[nt][2] * inv1); v1.y = to_tf32(o0[nt][3] * inv1);
            *(float2*)(outp  + dk) = v0;
            *(float2*)(outp8 + dk) = v1;
        }
    }
    {
        const float inv0 = 1.f / lB0;
        const float inv1 = 1.f / lB1;
        const int q = q0 + wid * 32 + 16 + r;
        float* outp  = (stream ? ctx1 : ctx0)
                     + ((size_t)(n * SDIM + q)) * DDIM + h * DKH;
        float* outp8 = outp + 8 * DDIM;
        #pragma unroll
        for (int nt = 0; nt < 8; nt++) {
            const int dk = nt * 8 + 2 * cq;
            float2 v0, v1;
            v0.x = to_tf32(o1[nt][0] * inv0); v0.y = to_tf32(o1[nt][1] * inv0);
            v1.x = to_tf32(o1[nt][2] * inv1); v1.y = to_tf32(o1[nt][3] * inv1);
            *(float2*)(outp  + dk) = v0;
            *(float2*)(outp8 + dk) = v1;
        }
    }
}

// ---------------------------------------------------------------------------
extern "C" void kernel_launch(void* const* d_in, const int* in_sizes, int n_in,
                              void* d_out, int out_size)
{
    const float* Qpoi = (const float*)d_in[0];
    const float* Qsvi = (const float*)d_in[1];
    const float* Kin  = (const float*)d_in[2];
    const float* Vin  = (const float*)d_in[3];
    const unsigned char* mask = (const unsigned char*)d_in[4];
    const float* wq_poi_w = (const float*)d_in[5];
    const float* wq_poi_b = (const float*)d_in[6];
    const float* wq_svi_w = (const float*)d_in[7];
    const float* wq_svi_b = (const float*)d_in[8];
    const float* wk_w = (const float*)d_in[9];
    const float* wk_b = (const float*)d_in[10];
    const float* wv_w = (const float*)d_in[11];
    const float* wv_b = (const float*)d_in[12];
    const float* fc_w = (const float*)d_in[13];
    const float* fc_b = (const float*)d_in[14];
    float* out = (float*)d_out;

    float *Qp, *Qs, *Kh, *Vh, *c0, *c1, *madd, *wt;
    cudaGetSymbolAddress((void**)&Qp, g_Qp);
    cudaGetSymbolAddress((void**)&Qs, g_Qs);
    cudaGetSymbolAddress((void**)&Kh, g_Kh);
    cudaGetSymbolAddress((void**)&Vh, g_Vh);
    cudaGetSymbolAddress((void**)&c0, g_ctx0);
    cudaGetSymbolAddress((void**)&c1, g_ctx1);
    cudaGetSymbolAddress((void**)&madd, g_madd);
    cudaGetSymbolAddress((void**)&wt, g_wt);

    float* wt_q_poi = wt + 0 * (size_t)DDIM * DDIM;
    float* wt_q_svi = wt + 1 * (size_t)DDIM * DDIM;
    float* wt_k     = wt + 2 * (size_t)DDIM * DDIM;
    float* wt_v     = wt + 3 * (size_t)DDIM * DDIM;
    float* wt_fc    = wt + 4 * (size_t)DDIM * DDIM;

    // 0a) canonicalize padding mask
    mask_expand_kernel<<<1, 1024>>>(mask, madd);

    // 0b) pre-round the 5 weight matrices to tf32
    W5 w5;
    w5.src[0] = (const float4*)wq_poi_w; w5.dst[0] = (float4*)wt_q_poi;
    w5.src[1] = (const float4*)wq_svi_w; w5.dst[1] = (float4*)wt_q_svi;
    w5.src[2] = (const float4*)wk_w;     w5.dst[2] = (float4*)wt_k;
    w5.src[3] = (const float4*)wv_w;     w5.dst[3] = (float4*)wt_v;
    w5.src[4] = (const float4*)fc_w;     w5.dst[4] = (float4*)wt_fc;
    wcvt_kernel<<<dim3(DDIM * DDIM / 4 / 256, 1, 5), 256>>>(w5);

    // 1) projections -> [N,H,S,DK] (one batched launch, z = 4)
    Batch4 proj;
    proj.A[0] = Qpoi; proj.W[0] = wt_q_poi; proj.bias[0] = wq_poi_b; proj.out[0] = Qp;
    proj.A[1] = Qsvi; proj.W[1] = wt_q_svi; proj.bias[1] = wq_svi_b; proj.out[1] = Qs;
    proj.A[2] = Kin;  proj.W[2] = wt_k;     proj.bias[2] = wk_b;     proj.out[2] = Kh;
    proj.A[3] = Vin;  proj.W[3] = wt_v;     proj.bias[3] = wv_b;     proj.out[3] = Vh;
    gemm_tc<0><<<dim3(DDIM / 128, (SDIM * NB) / 128, 4), 256>>>(proj);

    // 2) attention (tensor cores, tf32; both streams in z)
    const int smem = (2 * KSZ + 2 * VSZ + AQT * PS_STR + 2 * AKT) * (int)sizeof(float);
    cudaFuncSetAttribute((const void*)attn_tc,
                         cudaFuncAttributeMaxDynamicSharedMemorySize, smem);
    attn_tc<<<dim3(SDIM / AQT, NB * HH, 2), 128, smem>>>(Qp, Qs, Kh, Vh, madd, c0, c1);

    // 3) output FC -> [S,N,D] (one batched launch, z = 2)
    Batch4 fc;
    fc.A[0] = c0; fc.W[0] = wt_fc; fc.bias[0] = fc_b; fc.out[0] = out;
    fc.A[1] = c1; fc.W[1] = wt_fc; fc.bias[1] = fc_b; fc.out[1] = out + (size_t)SDIM * NB * DDIM;
    fc.A[2] = c0; fc.W[2] = wt_fc; fc.bias[2] = fc_b; fc.out[2] = out;  // unused
    fc.A[3] = c1; fc.W[3] = wt_fc; fc.bias[3] = fc_b; fc.out[3] = out + (size_t)SDIM * NB * DDIM;  // unused
    gemm_tc<1><<<dim3(DDIM / 128, (SDIM * NB) / 128, 2), 256>>>(fc);
}

// round 11
// speedup vs baseline: 1.7425x; 1.0361x over previous
#include <cuda_runtime.h>
#include <cstdint>

// Problem dims
#define SDIM 1024
#define NB   8
#define DDIM 1024
#define HH   16
#define DKH  64

// ---------------- scratch (device globals; no allocations allowed) ----------
__device__ float g_Qp[(size_t)NB * HH * SDIM * DKH];   // [N,H,S,DK] (tf32-rounded)
__device__ float g_Qs[(size_t)NB * HH * SDIM * DKH];
__device__ float g_Kh[(size_t)NB * HH * SDIM * DKH];
__device__ float g_Vh[(size_t)NB * HH * SDIM * DKH];
__device__ float g_ctx0[(size_t)NB * SDIM * DDIM];     // [N,S,D] (tf32-rounded)
__device__ float g_ctx1[(size_t)NB * SDIM * DDIM];
__device__ float g_madd[(size_t)NB * SDIM];            // 0 or -1e9 additive mask
__device__ int   g_ntiles[NB];                         // key tiles to process per batch
__device__ float g_wt[5][(size_t)DDIM * DDIM];         // tf32-rounded weights

// ---------------- mask canonicalization + tile-count ------------------------
__global__ void mask_expand_kernel(const unsigned char* __restrict__ m,
                                   float* __restrict__ madd,
                                   int* __restrict__ ntiles)
{
    __shared__ int s_big, s_nonmult4, s_anynz;
    const int t = threadIdx.x;               // 1024 threads, single block
    if (t == 0) { s_big = 0; s_nonmult4 = 0; s_anynz = 0; }
    __syncthreads();

    const int total = NB * SDIM;             // 8192 entries
    int big = 0, nonm4 = 0, anynz = 0;
    for (int i = t; i < total; i += 1024) {
        unsigned char b = m[i];
        if (b > 1) big = 1;
        if (b) { anynz = 1; if (i & 3) nonm4 = 1; }
    }
    if (big)   atomicOr(&s_big, 1);
    if (nonm4) atomicOr(&s_nonmult4, 1);
    if (anynz) atomicOr(&s_anynz, 1);
    __syncthreads();

    const bool width4 = s_big || !s_nonmult4 || !s_anynz;

    for (int i = t; i < total; i += 1024) {
        unsigned char v;
        if (width4) {
            v = (unsigned char)(m[4 * i] | m[4 * i + 1] | m[4 * i + 2] | m[4 * i + 3]);
        } else {
            v = m[i];
        }
        madd[i] = v ? -1e9f : 0.f;
    }
    __syncthreads();

    // per-batch key-tile count: if the mask is a contiguous suffix (padding),
    // tiles fully inside the padded region contribute exactly 0 and can be
    // skipped bit-identically. Otherwise fall back to all tiles.
    if (t < NB) {
        int cnt = 0;
        bool contig = true, seen = false;
        for (int j = 0; j < SDIM; j++) {
            const bool masked = (madd[t * SDIM + j] != 0.f);
            if (masked) seen = true;
            else { if (seen) contig = false; cnt++; }
        }
        int nt = (cnt + 63) >> 6;            // ceil(len / 64)
        if (!contig || cnt == 0) nt = SDIM / 64;
        ntiles[t] = nt;
    }
}

// ---------------- tf32 helpers ----------------------------------------------
__device__ __forceinline__ float to_tf32(float x) {
    float r;
    asm("cvt.rna.tf32.f32 %0, %1;" : "=f"(r) : "f"(x));
    return r;
}

__device__ __forceinline__ void mma_tf32_16x8x8(float* c, const uint32_t* a,
                                                const uint32_t* b)
{
    asm volatile(
        "mma.sync.aligned.m16n8k8.row.col.f32.tf32.tf32.f32 "
        "{%0,%1,%2,%3}, {%4,%5,%6,%7}, {%8,%9}, {%0,%1,%2,%3};"
        : "+f"(c[0]), "+f"(c[1]), "+f"(c[2]), "+f"(c[3])
        : "r"(a[0]), "r"(a[1]), "r"(a[2]), "r"(a[3]), "r"(b[0]), "r"(b[1]));
}

__device__ __forceinline__ void cp16(void* smem, const void* gmem) {
    uint32_t s = (uint32_t)__cvta_generic_to_shared(smem);
    asm volatile("cp.async.ca.shared.global [%0], [%1], 16;" :: "r"(s), "l"(gmem));
}

// ---------------- weight pre-rounding ----------------------------------------
struct W5 { const float4* src[5]; float4* dst[5]; };
__global__ void wcvt_kernel(W5 w)
{
    const int z = blockIdx.z;
    const float4* __restrict__ s = w.src[z];
    float4* __restrict__ d = w.dst[z];
    const int i = blockIdx.x * blockDim.x + threadIdx.x;   // 262144 float4
    float4 v = s[i];
    v.x = to_tf32(v.x); v.y = to_tf32(v.y);
    v.z = to_tf32(v.z); v.w = to_tf32(v.w);
    d[i] = v;
}

// k-permuted smem slab layout (16 k per row, 16 floats per row):
//   logical pos  p = (k%4)*4 + k/4; physical = p ^ (((row>>1)&3)<<2).
template <bool CVT>
__device__ __forceinline__ void store_slab(float* stage, int row, int c4i, float4 v)
{
    const int swz = ((row >> 1) & 3) << 2;
    float* p = stage + row * 16;
    if (CVT) {
        p[(c4i      ) ^ swz] = to_tf32(v.x);
        p[(c4i +  4) ^ swz] = to_tf32(v.y);
        p[(c4i +  8) ^ swz] = to_tf32(v.z);
        p[(c4i + 12) ^ swz] = to_tf32(v.w);
    } else {
        p[(c4i      ) ^ swz] = v.x;
        p[(c4i +  4) ^ swz] = v.y;
        p[(c4i +  8) ^ swz] = v.z;
        p[(c4i + 12) ^ swz] = v.w;
    }
}

// ---------------- batched, pipelined tensor-core GEMM -----------------------
struct Batch4 {
    const float* A[4];
    const float* W[4];
    const float* bias[4];
    float* out[4];
};

template <int MODE>
__global__ void __launch_bounds__(256, 2)
gemm_tc(Batch4 batch)
{
    constexpr int BM = 128, BN = 128, BK = 16, KD = 1024;
    __shared__ float As[2][BM * 16];
    __shared__ float Bs[2][BN * 16];

    const int z = blockIdx.z;
    const float* __restrict__ A    = batch.A[z];
    const float* __restrict__ W    = batch.W[z];
    const float* __restrict__ bias = batch.bias[z];
    float* __restrict__ out        = batch.out[z];

    const int tid  = threadIdx.x;
    const int wid  = tid >> 5;
    const int lane = tid & 31;
    const int wm = wid & 1;
    const int wn = wid >> 1;
    const int m0 = blockIdx.y * BM;
    const int n0 = blockIdx.x * BN;

    const int r  = lane >> 2;
    const int cq = lane & 3;
    const int cqo = cq * 4;

    const int lrow0 = tid >> 2;               // 0..63
    const int lrow1 = lrow0 + 64;             // 64..127
    const int c4i   = tid & 3;
    const int lc4   = c4i << 2;

    const float* Aptr = A + (size_t)m0 * KD;
    const float* Wptr = W + (size_t)n0 * KD;

    float acc[4][4][4];
    #pragma unroll
    for (int mt = 0; mt < 4; mt++)
        #pragma unroll
        for (int nt = 0; nt < 4; nt++)
            #pragma unroll
            for (int i = 0; i < 4; i++) acc[mt][nt][i] = 0.f;

    float4 pa0, pa1, pb0, pb1;

    pa0 = *(const float4*)(Aptr + (size_t)lrow0 * KD + lc4);
    pa1 = *(const float4*)(Aptr + (size_t)lrow1 * KD + lc4);
    pb0 = *(const float4*)(Wptr + (size_t)lrow0 * KD + lc4);
    pb1 = *(const float4*)(Wptr + (size_t)lrow1 * KD + lc4);
    store_slab<MODE == 0>(As[0], lrow0, c4i, pa0);
    store_slab<MODE == 0>(As[0], lrow1, c4i, pa1);
    store_slab<false>(Bs[0], lrow0, c4i, pb0);
    store_slab<false>(Bs[0], lrow1, c4i, pb1);
    __syncthreads();

    for (int it = 0; it < KD / BK; it++) {
        const int cur = it & 1;
        const int nxt = cur ^ 1;
        const bool more = (it + 1) < KD / BK;

        if (more) {
            const int kn = (it + 1) * BK;
            pa0 = *(const float4*)(Aptr + (size_t)lrow0 * KD + kn + lc4);
            pa1 = *(const float4*)(Aptr + (size_t)lrow1 * KD + kn + lc4);
            pb0 = *(const float4*)(Wptr + (size_t)lrow0 * KD + kn + lc4);
            pb1 = *(const float4*)(Wptr + (size_t)lrow1 * KD + kn + lc4);
        }

        const float* Asc = As[cur];
        const float* Bsc = Bs[cur];

        uint32_t bf0[4][2], bf1[4][2];
        #pragma unroll
        for (int nt = 0; nt < 4; nt++) {
            const int nrow = wn * 32 + nt * 8 + r;
            const int swz = ((nrow >> 1) & 3) << 2;
            const float4 bl = *(const float4*)(Bsc + nrow * 16 + (cqo ^ swz));
            bf0[nt][0] = __float_as_uint(bl.x);
            bf0[nt][1] = __float_as_uint(bl.y);
            bf1[nt][0] = __float_as_uint(bl.z);
            bf1[nt][1] = __float_as_uint(bl.w);
        }

        #pragma unroll
        for (int mt = 0; mt < 4; mt++) {
            const int mr = wm * 64 + mt * 16 + r;
            const int swz = ((mr >> 1) & 3) << 2;
            const float4 lf0 = *(const float4*)(Asc + mr * 16 + (cqo ^ swz));
            const float4 lf8 = *(const float4*)(Asc + (mr + 8) * 16 + (cqo ^ swz));

            uint32_t a0[4], a1[4];
            a0[0] = __float_as_uint(lf0.x); a0[1] = __float_as_uint(lf8.x);
            a0[2] = __float_as_uint(lf0.y); a0[3] = __float_as_uint(lf8.y);
            a1[0] = __float_as_uint(lf0.z); a1[1] = __float_as_uint(lf8.z);
            a1[2] = __float_as_uint(lf0.w); a1[3] = __float_as_uint(lf8.w);

            #pragma unroll
            for (int nt = 0; nt < 4; nt++)
                mma_tf32_16x8x8(acc[mt][nt], a0, bf0[nt]);
            #pragma unroll
            for (int nt = 0; nt < 4; nt++)
                mma_tf32_16x8x8(acc[mt][nt], a1, bf1[nt]);
        }

        if (more) {
            store_slab<MODE == 0>(As[nxt], lrow0, c4i, pa0);
            store_slab<MODE == 0>(As[nxt], lrow1, c4i, pa1);
            store_slab<false>(Bs[nxt], lrow0, c4i, pb0);
            store_slab<false>(Bs[nxt], lrow1, c4i, pb1);
        }
        __syncthreads();
    }

    const int cpair = (lane & 3) * 2;
    #pragma unroll
    for (int nt = 0; nt < 4; nt++) {
        const int dout = n0 + wn * 32 + nt * 8 + cpair;
        const float2 bb = *(const float2*)(bias + dout);
        #pragma unroll
        for (int mt = 0; mt < 4; mt++) {
            #pragma unroll
            for (int half = 0; half < 2; half++) {
                const int m = m0 + wm * 64 + mt * 16 + r + half * 8;
                float2 v;
                v.x = acc[mt][nt][half * 2 + 0] + bb.x;
                v.y = acc[mt][nt][half * 2 + 1] + bb.y;
                if (MODE == 0) {
                    v.x = to_tf32(v.x);
                    v.y = to_tf32(v.y);
                    const int s = m >> 3, n = m & 7;
                    const int h = dout >> 6, dk = dout & 63;
                    *(float2*)(out + ((size_t)((n * HH + h) * SDIM + s)) * DKH + dk) = v;
                } else {
                    const int n = m >> 10, s = m & 1023;
                    *(float2*)(out + ((size_t)(s * NB + n)) * DDIM + dout) = v;
                }
            }
        }
    }
}

// ---------------- tensor-core flash attention --------------------------------
// 128 threads, 4 warps; warp w owns 32 q rows (two m16 tiles). K/V fragment
// loads shared across both m-tiles. Double-buffered cp.async prefetch.
// Fully-padded key tiles are skipped (bit-identical; see mask kernel).
#define AQT 128
#define AKT 64
#define KS_STR 68
#define VS_STR 72
#define PS_STR 68
#define KSZ (AKT * KS_STR)
#define VSZ (AKT * VS_STR)

__global__ void __launch_bounds__(128, 2)
attn_tc(const float* __restrict__ Qp, const float* __restrict__ Qsv,
        const float* __restrict__ Kh, const float* __restrict__ Vh,
        const float* __restrict__ maddg, const int* __restrict__ ntilesg,
        float* __restrict__ ctx0, float* __restrict__ ctx1)
{
    extern __shared__ float sm[];
    float* KsB   = sm;                        // [2][64][KS_STR]
    float* VsB   = KsB + 2 * KSZ;             // [2][64][VS_STR]
    float* Ps    = VsB + 2 * VSZ;             // [128][PS_STR]
    float* maddB = Ps + AQT * PS_STR;         // [2][64]

    const int nh = blockIdx.y;
    const int n  = nh / HH;
    const int stream = blockIdx.z;
    const int q0 = blockIdx.x * AQT;
    const int tid = threadIdx.x;
    const int wid = tid >> 5;                 // 0..3
    const int lane = tid & 31;
    const int r  = lane >> 2;
    const int cq = lane & 3;

    const int ntiles = ntilesg[n];

    const float* Qb = (stream ? Qsv : Qp) + (size_t)nh * SDIM * DKH;
    const float* Kb = Kh + (size_t)nh * SDIM * DKH;
    const float* Vb = Vh + (size_t)nh * SDIM * DKH;
    const float* mrow = maddg + n * SDIM;

    // Q fragments for the warp's two m16 tiles (pre-rounded -> raw loads)
    uint32_t qf0[8][4], qf1[8][4];
    {
        const float* qa = Qb + (size_t)(q0 + wid * 32 + r) * DKH;
        const float* qb = qa + 8 * DKH;
        const float* qc = qa + 16 * DKH;
        const float* qd = qa + 24 * DKH;
        #pragma unroll
        for (int ks = 0; ks < 8; ks++) {
            qf0[ks][0] = __float_as_uint(qa[ks * 8 + cq]);
            qf0[ks][1] = __float_as_uint(qb[ks * 8 + cq]);
            qf0[ks][2] = __float_as_uint(qa[ks * 8 + cq + 4]);
            qf0[ks][3] = __float_as_uint(qb[ks * 8 + cq + 4]);
            qf1[ks][0] = __float_as_uint(qc[ks * 8 + cq]);
            qf1[ks][1] = __float_as_uint(qd[ks * 8 + cq]);
            qf1[ks][2] = __float_as_uint(qc[ks * 8 + cq + 4]);
            qf1[ks][3] = __float_as_uint(qd[ks * 8 + cq + 4]);
        }
    }

    float o0[8][4], o1[8][4];
    #pragma unroll
    for (int nt = 0; nt < 8; nt++)
        #pragma unroll
        for (int i = 0; i < 4; i++) { o0[nt][i] = 0.f; o1[nt][i] = 0.f; }
    float mA0 = -1e30f, mA1 = -1e30f, lA0 = 0.f, lA1 = 0.f;   // m-tile 0
    float mB0 = -1e30f, mB1 = -1e30f, lB0 = 0.f, lB1 = 0.f;   // m-tile 1

    // prologue fill: stage 0, k0 = 0
    {
        const float* ksrc = Kb;
        const float* vsrc = Vb;
        #pragma unroll
        for (int i = 0; i < 8; i++) {
            const int idx = tid + 128 * i;         // 0..1023
            const int row = idx >> 4;
            const int c4  = (idx & 15) << 2;
            cp16(KsB + row * KS_STR + c4, ksrc + idx * 4);
            cp16(VsB + row * VS_STR + c4, vsrc + idx * 4);
        }
        if (tid < AKT) maddB[tid] = mrow[tid];
        asm volatile("cp.async.wait_all;" ::: "memory");
    }
    __syncthreads();

    for (int kt = 0; kt < ntiles; kt++) {
        const int cur = kt & 1;
        const bool more = (kt + 1) < ntiles;

        // prefetch next K/V tile into the other stage (waited at loop end)
        if (more) {
            const int kn = (kt + 1) * AKT;
            const float* ksrc = Kb + (size_t)kn * DKH;
            const float* vsrc = Vb + (size_t)kn * DKH;
            float* kd = KsB + (cur ^ 1) * KSZ;
            float* vd = VsB + (cur ^ 1) * VSZ;
            #pragma unroll
            for (int i = 0; i < 8; i++) {
                const int idx = tid + 128 * i;
                const int row = idx >> 4;
                const int c4  = (idx & 15) << 2;
                cp16(kd + row * KS_STR + c4, ksrc + idx * 4);
                cp16(vd + row * VS_STR + c4, vsrc + idx * 4);
            }
            if (tid < AKT) maddB[(cur ^ 1) * AKT + tid] = mrow[kn + tid];
        }

        const float* Kst = KsB + cur * KSZ;
        const float* Vst = VsB + cur * VSZ;
        const float* madd = maddB + cur * AKT;

        // ---- scores for both m-tiles; each K fragment feeds 2 MMAs ----
        float sc0[8][4], sc1[8][4];
        #pragma unroll
        for (int nt = 0; nt < 8; nt++)
            #pragma unroll
            for (int i = 0; i < 4; i++) { sc0[nt][i] = 0.f; sc1[nt][i] = 0.f; }

        #pragma unroll
        for (int ks = 0; ks < 8; ks++) {
            const int kb = ks * 8;
            #pragma unroll
            for (int nt = 0; nt < 8; nt++) {
                uint32_t b[2];
                const float* p = Kst + (nt * 8 + r) * KS_STR + kb + cq;
                b[0] = __float_as_uint(p[0]);
                b[1] = __float_as_uint(p[4]);
                mma_tf32_16x8x8(sc0[nt], qf0[ks], b);
                mma_tf32_16x8x8(sc1[nt], qf1[ks], b);
            }
        }

        // ---- online softmax, m-tile 0 ----
        {
            float tmax0 = -1e30f, tmax1 = -1e30f;
            #pragma unroll
            for (int nt = 0; nt < 8; nt++) {
                const int j = nt * 8 + 2 * cq;
                const float ma = madd[j], mb = madd[j + 1];
                sc0[nt][0] = sc0[nt][0] * 0.125f + ma;
                sc0[nt][1] = sc0[nt][1] * 0.125f + mb;
                sc0[nt][2] = sc0[nt][2] * 0.125f + ma;
                sc0[nt][3] = sc0[nt][3] * 0.125f + mb;
                tmax0 = fmaxf(tmax0, fmaxf(sc0[nt][0], sc0[nt][1]));
                tmax1 = fmaxf(tmax1, fmaxf(sc0[nt][2], sc0[nt][3]));
            }
            tmax0 = fmaxf(tmax0, __shfl_xor_sync(0xffffffffu, tmax0, 1));
            tmax0 = fmaxf(tmax0, __shfl_xor_sync(0xffffffffu, tmax0, 2));
            tmax1 = fmaxf(tmax1, __shfl_xor_sync(0xffffffffu, tmax1, 1));
            tmax1 = fmaxf(tmax1, __shfl_xor_sync(0xffffffffu, tmax1, 2));

            const float mn0 = fmaxf(mA0, tmax0);
            const float mn1 = fmaxf(mA1, tmax1);
            const float cr0 = __expf(mA0 - mn0);
            const float cr1 = __expf(mA1 - mn1);
            mA0 = mn0; mA1 = mn1;

            float ls0 = 0.f, ls1 = 0.f;
            float* prow0 = Ps + (wid * 32 + r) * PS_STR + 2 * cq;
            float* prow8 = prow0 + 8 * PS_STR;
            #pragma unroll
            for (int nt = 0; nt < 8; nt++) {
                const float p0 = __expf(sc0[nt][0] - mn0);
                const float p1 = __expf(sc0[nt][1] - mn0);
                const float p2 = __expf(sc0[nt][2] - mn1);
                const float p3 = __expf(sc0[nt][3] - mn1);
                ls0 += p0 + p1;
                ls1 += p2 + p3;
                float2 w0, w1;
                w0.x = to_tf32(p0); w0.y = to_tf32(p1);
                w1.x = to_tf32(p2); w1.y = to_tf32(p3);
                *(float2*)(prow0 + nt * 8) = w0;
                *(float2*)(prow8 + nt * 8) = w1;
                o0[nt][0] *= cr0; o0[nt][1] *= cr0;
                o0[nt][2] *= cr1; o0[nt][3] *= cr1;
            }
            ls0 += __shfl_xor_sync(0xffffffffu, ls0, 1);
            ls0 += __shfl_xor_sync(0xffffffffu, ls0, 2);
            ls1 += __shfl_xor_sync(0xffffffffu, ls1, 1);
            ls1 += __shfl_xor_sync(0xffffffffu, ls1, 2);
            lA0 = lA0 * cr0 + ls0;
            lA1 = lA1 * cr1 + ls1;
        }

        // ---- online softmax, m-tile 1 ----
        {
            float tmax0 = -1e30f, tmax1 = -1e30f;
            #pragma unroll
            for (int nt = 0; nt < 8; nt++) {
                const int j = nt * 8 + 2 * cq;
                const float ma = madd[j], mb = madd[j + 1];
                sc1[nt][0] = sc1[nt][0] * 0.125f + ma;
                sc1[nt][1] = sc1[nt][1] * 0.125f + mb;
                sc1[nt][2] = sc1[nt][2] * 0.125f + ma;
                sc1[nt][3] = sc1[nt][3] * 0.125f + mb;
                tmax0 = fmaxf(tmax0, fmaxf(sc1[nt][0], sc1[nt][1]));
                tmax1 = fmaxf(tmax1, fmaxf(sc1[nt][2], sc1[nt][3]));
            }
            tmax0 = fmaxf(tmax0, __shfl_xor_sync(0xffffffffu, tmax0, 1));
            tmax0 = fmaxf(tmax0, __shfl_xor_sync(0xffffffffu, tmax0, 2));
            tmax1 = fmaxf(tmax1, __shfl_xor_sync(0xffffffffu, tmax1, 1));
            tmax1 = fmaxf(tmax1, __shfl_xor_sync(0xffffffffu, tmax1, 2));

            const float mn0 = fmaxf(mB0, tmax0);
            const float mn1 = fmaxf(mB1, tmax1);
            const float cr0 = __expf(mB0 - mn0);
            const float cr1 = __expf(mB1 - mn1);
            mB0 = mn0; mB1 = mn1;

            float ls0 = 0.f, ls1 = 0.f;
            float* prow0 = Ps + (wid * 32 + 16 + r) * PS_STR + 2 * cq;
            float* prow8 = prow0 + 8 * PS_STR;
            #pragma unroll
            for (int nt = 0; nt < 8; nt++) {
                const float p0 = __expf(sc1[nt][0] - mn0);
                const float p1 = __expf(sc1[nt][1] - mn0);
                const float p2 = __expf(sc1[nt][2] - mn1);
                const float p3 = __expf(sc1[nt][3] - mn1);
                ls0 += p0 + p1;
                ls1 += p2 + p3;
                float2 w0, w1;
                w0.x = to_tf32(p0); w0.y = to_tf32(p1);
                w1.x = to_tf32(p2); w1.y = to_tf32(p3);
                *(float2*)(prow0 + nt * 8) = w0;
                *(float2*)(prow8 + nt * 8) = w1;
                o1[nt][0] *= cr0; o1[nt][1] *= cr0;
                o1[nt][2] *= cr1; o1[nt][3] *= cr1;
            }
            ls0 += __shfl_xor_sync(0xffffffffu, ls0, 1);
            ls0 += __shfl_xor_sync(0xffffffffu, ls0, 2);
            ls1 += __shfl_xor_sync(0xffffffffu, ls1, 1);
            ls1 += __shfl_xor_sync(0xffffffffu, ls1, 2);
            lB0 = lB0 * cr0 + ls0;
            lB1 = lB1 * cr1 + ls1;
        }

        __syncwarp();   // Ps rows are warp-private; order STS->LDS

        // ---- O += P @ V; each V fragment feeds 2 MMAs ----
        #pragma unroll
        for (int ks = 0; ks < 8; ks++) {
            const int kb = ks * 8;
            uint32_t a0[4], a1[4];
            const float* pa0 = Ps + (wid * 32 + r) * PS_STR + kb;
            a0[0] = __float_as_uint(pa0[cq]);
            a0[1] = __float_as_uint(pa0[8 * PS_STR + cq]);
            a0[2] = __float_as_uint(pa0[cq + 4]);
            a0[3] = __float_as_uint(pa0[8 * PS_STR + cq + 4]);
            const float* pa1 = pa0 + 16 * PS_STR;
            a1[0] = __float_as_uint(pa1[cq]);
            a1[1] = __float_as_uint(pa1[8 * PS_STR + cq]);
            a1[2] = __float_as_uint(pa1[cq + 4]);
            a1[3] = __float_as_uint(pa1[8 * PS_STR + cq + 4]);
            #pragma unroll
            for (int nt = 0; nt < 8; nt++) {
                uint32_t b[2];
                const float* pv = Vst + (kb + cq) * VS_STR + nt * 8 + r;
                b[0] = __float_as_uint(pv[0]);
                b[1] = __float_as_uint(pv[4 * VS_STR]);
                mma_tf32_16x8x8(o0[nt], a0, b);
                mma_tf32_16x8x8(o1[nt], a1, b);
            }
        }

        asm volatile("cp.async.wait_all;" ::: "memory");
        __syncthreads();   // stage swap + P reuse
    }

    // ---- epilogue: write tf32-rounded ctx (consumed by FC gemm) ----
    const int h = nh % HH;
    {
        const float inv0 = 1.f / lA0;
        const float inv1 = 1.f / lA1;
        const int q = q0 + wid * 32 + r;
        float* outp  = (stream ? ctx1 : ctx0)
                     + ((size_t)(n * SDIM + q)) * DDIM + h * DKH;
        float* outp8 = outp + 8 * DDIM;
        #pragma unroll
        for (int nt = 0; nt < 8; nt++) {
            const int dk = nt * 8 + 2 * cq;
            float2 v0, v1;
            v0.x = to_tf32(o0[nt][0] * inv0); v0.y = to_tf32(o0[nt][1] * inv0);
            v1.x = to_tf32(o0[nt][2] * inv1); v1.y = to_tf32(o0[nt][3] * inv1);
            *(float2*)(outp  + dk) = v0;
            *(float2*)(outp8 + dk) = v1;
        }
    }
    {
        const float inv0 = 1.f / lB0;
        const float inv1 = 1.f / lB1;
        const int q = q0 + wid * 32 + 16 + r;
        float* outp  = (stream ? ctx1 : ctx0)
                     + ((size_t)(n * SDIM + q)) * DDIM + h * DKH;
        float* outp8 = outp + 8 * DDIM;
        #pragma unroll
        for (int nt = 0; nt < 8; nt++) {
            const int dk = nt * 8 + 2 * cq;
            float2 v0, v1;
            v0.x = to_tf32(o1[nt][0] * inv0); v0.y = to_tf32(o1[nt][1] * inv0);
            v1.x = to_tf32(o1[nt][2] * inv1); v1.y = to_tf32(o1[nt][3] * inv1);
            *(float2*)(outp  + dk) = v0;
            *(float2*)(outp8 + dk) = v1;
        }
    }
}

// ---------------------------------------------------------------------------
extern "C" void kernel_launch(void* const* d_in, const int* in_sizes, int n_in,
                              void* d_out, int out_size)
{
    const float* Qpoi = (const float*)d_in[0];
    const float* Qsvi = (const float*)d_in[1];
    const float* Kin  = (const float*)d_in[2];
    const float* Vin  = (const float*)d_in[3];
    const unsigned char* mask = (const unsigned char*)d_in[4];
    const float* wq_poi_w = (const float*)d_in[5];
    const float* wq_poi_b = (const float*)d_in[6];
    const float* wq_svi_w = (const float*)d_in[7];
    const float* wq_svi_b = (const float*)d_in[8];
    const float* wk_w = (const float*)d_in[9];
    const float* wk_b = (const float*)d_in[10];
    const float* wv_w = (const float*)d_in[11];
    const float* wv_b = (const float*)d_in[12];
    const float* fc_w = (const float*)d_in[13];
    const float* fc_b = (const float*)d_in[14];
    float* out = (float*)d_out;

    float *Qp, *Qs, *Kh, *Vh, *c0, *c1, *madd, *wt;
    int* ntl;
    cudaGetSymbolAddress((void**)&Qp, g_Qp);
    cudaGetSymbolAddress((void**)&Qs, g_Qs);
    cudaGetSymbolAddress((void**)&Kh, g_Kh);
    cudaGetSymbolAddress((void**)&Vh, g_Vh);
    cudaGetSymbolAddress((void**)&c0, g_ctx0);
    cudaGetSymbolAddress((void**)&c1, g_ctx1);
    cudaGetSymbolAddress((void**)&madd, g_madd);
    cudaGetSymbolAddress((void**)&ntl, g_ntiles);
    cudaGetSymbolAddress((void**)&wt, g_wt);

    float* wt_q_poi = wt + 0 * (size_t)DDIM * DDIM;
    float* wt_q_svi = wt + 1 * (size_t)DDIM * DDIM;
    float* wt_k     = wt + 2 * (size_t)DDIM * DDIM;
    float* wt_v     = wt + 3 * (size_t)DDIM * DDIM;
    float* wt_fc    = wt + 4 * (size_t)DDIM * DDIM;

    // 0a) canonicalize padding mask + per-batch tile counts
    mask_expand_kernel<<<1, 1024>>>(mask, madd, ntl);

    // 0b) pre-round the 5 weight matrices to tf32
    W5 w5;
    w5.src[0] = (const float4*)wq_poi_w; w5.dst[0] = (float4*)wt_q_poi;
    w5.src[1] = (const float4*)wq_svi_w; w5.dst[1] = (float4*)wt_q_svi;
    w5.src[2] = (const float4*)wk_w;     w5.dst[2] = (float4*)wt_k;
    w5.src[3] = (const float4*)wv_w;     w5.dst[3] = (float4*)wt_v;
    w5.src[4] = (const float4*)fc_w;     w5.dst[4] = (float4*)wt_fc;
    wcvt_kernel<<<dim3(DDIM * DDIM / 4 / 256, 1, 5), 256>>>(w5);

    // 1) projections -> [N,H,S,DK] (one batched launch, z = 4)
    Batch4 proj;
    proj.A[0] = Qpoi; proj.W[0] = wt_q_poi; proj.bias[0] = wq_poi_b; proj.out[0] = Qp;
    proj.A[1] = Qsvi; proj.W[1] = wt_q_svi; proj.bias[1] = wq_svi_b; proj.out[1] = Qs;
    proj.A[2] = Kin;  proj.W[2] = wt_k;     proj.bias[2] = wk_b;     proj.out[2] = Kh;
    proj.A[3] = Vin;  proj.W[3] = wt_v;     proj.bias[3] = wv_b;     proj.out[3] = Vh;
    gemm_tc<0><<<dim3(DDIM / 128, (SDIM * NB) / 128, 4), 256>>>(proj);

    // 2) attention (tensor cores, tf32; both streams in z; padded tiles skipped)
    const int smem = (2 * KSZ + 2 * VSZ + AQT * PS_STR + 2 * AKT) * (int)sizeof(float);
    cudaFuncSetAttribute((const void*)attn_tc,
                         cudaFuncAttributeMaxDynamicSharedMemorySize, smem);
    attn_tc<<<dim3(SDIM / AQT, NB * HH, 2), 128, smem>>>(Qp, Qs, Kh, Vh, madd, ntl, c0, c1);

    // 3) output FC -> [S,N,D] (one batched launch, z = 2)
    Batch4 fc;
    fc.A[0] = c0; fc.W[0] = wt_fc; fc.bias[0] = fc_b; fc.out[0] = out;
    fc.A[1] = c1; fc.W[1] = wt_fc; fc.bias[1] = fc_b; fc.out[1] = out + (size_t)SDIM * NB * DDIM;
    fc.A[2] = c0; fc.W[2] = wt_fc; fc.bias[2] = fc_b; fc.out[2] = out;  // unused
    fc.A[3] = c1; fc.W[3] = wt_fc; fc.bias[3] = fc_b; fc.out[3] = out + (size_t)SDIM * NB * DDIM;  // unused
    gemm_tc<1><<<dim3(DDIM / 128, (SDIM * NB) / 128, 2), 256>>>(fc);
}